// round 1
// baseline (speedup 1.0000x reference)
#include <cuda_runtime.h>
#include <cstdint>

#define NK   10000
#define NE   100000
#define D    128
#define DD   (128*128)
#define EDG  1600000

// ---------------- scratch (static __device__ — no allocations allowed) ----------------
__device__ float g_ii2[NK * D];
__device__ float g_neigh_b[NE * D];
__device__ float g_neigh_c[NE * D];
__device__ float g_tmp[NE * D];
__device__ float g_hiI[NE * D];
__device__ float g_hiS[NE * D];
__device__ float g_srccom[NE * D];
__device__ int   g_deg[NE];
__device__ int   g_rowptr[NE + 1];
__device__ int   g_cursor[NE];
__device__ int   g_esrc[EDG];
__device__ float g_ew[EDG];
__device__ float g_M1[DD], g_M2[DD], g_M3[DD], g_M4[DD];
__device__ float g_c1[D], g_c2[D];

// ---------------- f32x2 helpers ----------------
__device__ __forceinline__ uint64_t fma2(uint64_t a, uint64_t b, uint64_t c) {
    uint64_t d;
    asm("fma.rn.f32x2 %0, %1, %2, %3;" : "=l"(d) : "l"(a), "l"(b), "l"(c));
    return d;
}
__device__ __forceinline__ uint64_t dup2(float a) {
    uint64_t d;
    asm("mov.b64 %0, {%1, %1};" : "=l"(d) : "f"(a));
    return d;
}
__device__ __forceinline__ float2 unpack2(uint64_t v) {
    float2 r;
    asm("mov.b64 {%0, %1}, %2;" : "=f"(r.x), "=f"(r.y) : "l"(v));
    return r;
}

// ---------------- weight folding: M = A @ B  (all 128x128, row-major) ----------------
__global__ void fold_mats(const float* __restrict__ w2, const float* __restrict__ ekS1,
                          const float* __restrict__ ekN1, const float* __restrict__ w3,
                          const float* __restrict__ eeS1, const float* __restrict__ eeN1) {
    int mat = blockIdx.y;
    const float* A; const float* B; float* O;
    if (mat == 0)      { A = w2; B = ekS1; O = g_M1; }
    else if (mat == 1) { A = w2; B = ekN1; O = g_M2; }
    else if (mat == 2) { A = w3; B = eeS1; O = g_M3; }
    else               { A = w3; B = eeN1; O = g_M4; }
    int idx = blockIdx.x * blockDim.x + threadIdx.x;   // 64 blocks * 256 = 16384
    int n = idx >> 7, k = idx & 127;
    float acc = 0.f;
#pragma unroll 8
    for (int j = 0; j < 128; ++j)
        acc += A[n * 128 + j] * B[j * 128 + k];
    O[idx] = acc;
}

__global__ void fold_bias(const float* __restrict__ w2, const float* __restrict__ w2b,
                          const float* __restrict__ ekb1, const float* __restrict__ w3,
                          const float* __restrict__ w3b, const float* __restrict__ eeb1) {
    int t = threadIdx.x;  // 128
    float a = 0.f, b = 0.f;
#pragma unroll 8
    for (int j = 0; j < 128; ++j) {
        a += w2[t * 128 + j] * ekb1[j];
        b += w3[t * 128 + j] * eeb1[j];
    }
    g_c1[t] = a + w2b[t];
    g_c2[t] = b + w3b[t];
}

// ---------------- CSR build ----------------
__global__ void zero_deg(int n) {
    int i = blockIdx.x * blockDim.x + threadIdx.x;
    if (i < n) g_deg[i] = 0;
}

__global__ void count_kernel(const int* __restrict__ dst, int E) {
    int i = blockIdx.x * blockDim.x + threadIdx.x;
    if (i < E) atomicAdd(&g_deg[dst[i]], 1);
}

// single-block exclusive scan of g_deg[0..n) -> g_rowptr / g_cursor, 4 elems/thread
__global__ void scan_kernel(int n) {
    __shared__ int wsum[32];
    int tid = threadIdx.x, lane = tid & 31, wid = tid >> 5;
    int carry = 0;
    for (int base = 0; base < n; base += 4096) {
        int idx = base + tid * 4;
        int v0 = (idx + 0 < n) ? g_deg[idx + 0] : 0;
        int v1 = (idx + 1 < n) ? g_deg[idx + 1] : 0;
        int v2 = (idx + 2 < n) ? g_deg[idx + 2] : 0;
        int v3 = (idx + 3 < n) ? g_deg[idx + 3] : 0;
        int t1 = v0, t2 = v0 + v1, t3 = t2 + v2, ts = t3 + v3;
        int inc = ts;
#pragma unroll
        for (int o = 1; o < 32; o <<= 1) {
            int x = __shfl_up_sync(0xFFFFFFFFu, inc, o);
            if (lane >= o) inc += x;
        }
        if (lane == 31) wsum[wid] = inc;
        __syncthreads();
        if (wid == 0) {
            int si = wsum[lane];
#pragma unroll
            for (int o = 1; o < 32; o <<= 1) {
                int x = __shfl_up_sync(0xFFFFFFFFu, si, o);
                if (lane >= o) si += x;
            }
            wsum[lane] = si;
        }
        __syncthreads();
        int wexc = wid ? wsum[wid - 1] : 0;
        int texc = carry + wexc + inc - ts;
        if (idx + 0 < n) { g_rowptr[idx + 0] = texc;      g_cursor[idx + 0] = texc; }
        if (idx + 1 < n) { g_rowptr[idx + 1] = texc + t1; g_cursor[idx + 1] = texc + t1; }
        if (idx + 2 < n) { g_rowptr[idx + 2] = texc + t2; g_cursor[idx + 2] = texc + t2; }
        if (idx + 3 < n) { g_rowptr[idx + 3] = texc + t3; g_cursor[idx + 3] = texc + t3; }
        carry += wsum[31];
        __syncthreads();
    }
    if (tid == 0) g_rowptr[n] = carry;
}

__global__ void scatter_kernel(const int* __restrict__ src, const int* __restrict__ dst,
                               const float* __restrict__ ew, int E) {
    int i = blockIdx.x * blockDim.x + threadIdx.x;
    if (i >= E) return;
    int d = dst[i];
    int pos = atomicAdd(&g_cursor[d], 1);
    g_esrc[pos] = src[i];
    if (ew) g_ew[pos] = ew[i];
}

// ---------------- mean aggregation: warp per destination node ----------------
template <int WEIGHTED>
__global__ void aggregate_kernel(const float* __restrict__ src, float* __restrict__ out, int n) {
    int gw = (blockIdx.x * blockDim.x + threadIdx.x) >> 5;
    int lane = threadIdx.x & 31;
    if (gw >= n) return;
    int s0 = g_rowptr[gw], s1 = g_rowptr[gw + 1];
    float4 acc = make_float4(0.f, 0.f, 0.f, 0.f);
    for (int j = s0; j < s1; ++j) {
        int sidx = g_esrc[j];
        float4 v = *(const float4*)(src + (size_t)sidx * D + lane * 4);
        float w = WEIGHTED ? g_ew[j] : 1.0f;
        acc.x += v.x * w; acc.y += v.y * w; acc.z += v.z * w; acc.w += v.w * w;
    }
    float inv = 1.0f / fmaxf((float)(s1 - s0), 1.0f);
    acc.x *= inv; acc.y *= inv; acc.z *= inv; acc.w *= inv;
    *(float4*)(out + (size_t)gw * D + lane * 4) = acc;
}

// ---------------- fused dual-A GEMM: C = act(A1@W1^T + A2@W2^T + bias) ----------------
// A1,A2: [M,128] row-major.  W1,W2: [128, ldw] row-major (W[n][k]).  N=128, K=256.
// ACT: 0 none, 1 relu, 2 leaky(0.2)
template <int ACT>
__global__ void __launch_bounds__(256, 2) gemm_dual(
    const float* __restrict__ A1, const float* __restrict__ A2,
    const float* __restrict__ W1, int ldw1,
    const float* __restrict__ W2, int ldw2,
    const float* __restrict__ bias, float* __restrict__ C, int M)
{
    __shared__ float As[16][132];
    __shared__ float Bs[16][132];
    int tid = threadIdx.x;
    int mb = blockIdx.x * 128;
    int tn = (tid & 15) * 8;
    int tm = (tid >> 4) * 8;

    uint64_t acc[8][4];
#pragma unroll
    for (int i = 0; i < 8; ++i)
#pragma unroll
        for (int j = 0; j < 4; ++j) acc[i][j] = 0ull;

    for (int t = 0; t < 16; ++t) {
        const float* A = (t < 8) ? A1 : A2;
        const float* W = (t < 8) ? W1 : W2;
        int ldw = (t < 8) ? ldw1 : ldw2;
        int k0 = (t & 7) * 16;
#pragma unroll
        for (int u = 0; u < 2; ++u) {
            int s = u * 256 + tid;
            int r = s >> 2, c = s & 3;
            int row = mb + r;
            float4 v = (row < M) ? *(const float4*)(A + (size_t)row * D + k0 + c * 4)
                                 : make_float4(0.f, 0.f, 0.f, 0.f);
            As[c * 4 + 0][r] = v.x; As[c * 4 + 1][r] = v.y;
            As[c * 4 + 2][r] = v.z; As[c * 4 + 3][r] = v.w;
            float4 w = *(const float4*)(W + (size_t)r * ldw + k0 + c * 4);
            Bs[c * 4 + 0][r] = w.x; Bs[c * 4 + 1][r] = w.y;
            Bs[c * 4 + 2][r] = w.z; Bs[c * 4 + 3][r] = w.w;
        }
        __syncthreads();
#pragma unroll
        for (int k = 0; k < 16; ++k) {
            float4 a0 = *(const float4*)&As[k][tm];
            float4 a1 = *(const float4*)&As[k][tm + 4];
            ulonglong2 bb0 = *(const ulonglong2*)&Bs[k][tn];
            ulonglong2 bb1 = *(const ulonglong2*)&Bs[k][tn + 4];
            uint64_t b[4] = { bb0.x, bb0.y, bb1.x, bb1.y };
            uint64_t ad[8] = { dup2(a0.x), dup2(a0.y), dup2(a0.z), dup2(a0.w),
                               dup2(a1.x), dup2(a1.y), dup2(a1.z), dup2(a1.w) };
#pragma unroll
            for (int i = 0; i < 8; ++i)
#pragma unroll
                for (int j = 0; j < 4; ++j)
                    acc[i][j] = fma2(ad[i], b[j], acc[i][j]);
        }
        __syncthreads();
    }

    float4 b0v = *(const float4*)(bias + tn);
    float4 b1v = *(const float4*)(bias + tn + 4);
    float bv[8] = { b0v.x, b0v.y, b0v.z, b0v.w, b1v.x, b1v.y, b1v.z, b1v.w };
#pragma unroll
    for (int i = 0; i < 8; ++i) {
        int row = mb + tm + i;
        if (row >= M) continue;
        float o[8];
#pragma unroll
        for (int j = 0; j < 4; ++j) {
            float2 f = unpack2(acc[i][j]);
            o[2 * j + 0] = f.x + bv[2 * j + 0];
            o[2 * j + 1] = f.y + bv[2 * j + 1];
        }
#pragma unroll
        for (int j = 0; j < 8; ++j) {
            if (ACT == 1) o[j] = fmaxf(o[j], 0.f);
            else if (ACT == 2) o[j] = (o[j] >= 0.f) ? o[j] : 0.2f * o[j];
        }
        *(float4*)(C + (size_t)row * D + tn)     = make_float4(o[0], o[1], o[2], o[3]);
        *(float4*)(C + (size_t)row * D + tn + 4) = make_float4(o[4], o[5], o[6], o[7]);
    }
}

// ---------------- launch ----------------
extern "C" void kernel_launch(void* const* d_in, const int* in_sizes, int n_in,
                              void* d_out, int out_size) {
    const float* ii      = (const float*)d_in[0];
    const float* e_emb   = (const float*)d_in[1];
    const float* k_emb   = (const float*)d_in[2];
    const float* cf_ew   = (const float*)d_in[3];
    const int*   b_src   = (const int*)d_in[4];
    const int*   b_dst   = (const int*)d_in[5];
    const int*   c_src   = (const int*)d_in[6];
    const int*   c_dst   = (const int*)d_in[7];
    const float* ek_self = (const float*)d_in[8];
    const float* ek_neigh= (const float*)d_in[9];
    const float* ek_bias = (const float*)d_in[10];
    const float* ee_self = (const float*)d_in[11];
    const float* ee_neigh= (const float*)d_in[12];
    const float* ee_bias = (const float*)d_in[13];
    const float* w1W = (const float*)d_in[14];
    const float* w1b = (const float*)d_in[15];
    const float* w2W = (const float*)d_in[16];
    const float* w2b = (const float*)d_in[17];
    const float* w3W = (const float*)d_in[18];
    const float* w3b = (const float*)d_in[19];
    const float* w4W = (const float*)d_in[20];
    const float* w4b = (const float*)d_in[21];
    const float* combW = (const float*)d_in[22];
    const float* combb = (const float*)d_in[23];
    float* out = (float*)d_out;

    int n_k = in_sizes[0] / D;
    int n_e = in_sizes[1] / D;
    int E   = in_sizes[4];

    float *p_ii2, *p_nb, *p_nc, *p_tmp, *p_hiI, *p_hiS, *p_sc;
    float *p_M1, *p_M2, *p_M3, *p_M4, *p_c1, *p_c2;
    cudaGetSymbolAddress((void**)&p_ii2, g_ii2);
    cudaGetSymbolAddress((void**)&p_nb,  g_neigh_b);
    cudaGetSymbolAddress((void**)&p_nc,  g_neigh_c);
    cudaGetSymbolAddress((void**)&p_tmp, g_tmp);
    cudaGetSymbolAddress((void**)&p_hiI, g_hiI);
    cudaGetSymbolAddress((void**)&p_hiS, g_hiS);
    cudaGetSymbolAddress((void**)&p_sc,  g_srccom);
    cudaGetSymbolAddress((void**)&p_M1,  g_M1);
    cudaGetSymbolAddress((void**)&p_M2,  g_M2);
    cudaGetSymbolAddress((void**)&p_M3,  g_M3);
    cudaGetSymbolAddress((void**)&p_M4,  g_M4);
    cudaGetSymbolAddress((void**)&p_c1,  g_c1);
    cudaGetSymbolAddress((void**)&p_c2,  g_c2);

    int gE  = (E + 255) / 256;
    int gNe = (n_e + 255) / 256;
    int gAgg = (n_e * 32 + 255) / 256;
    int gbK = (n_k + 127) / 128;
    int gbE = (n_e + 127) / 128;

    // fold layer-1 weights through w2 / w3
    fold_mats<<<dim3(64, 4), 256>>>(w2W, ek_self + DD, ek_neigh + DD,
                                    w3W, ee_self + DD, ee_neigh + DD);
    fold_bias<<<1, 128>>>(w2W, w2b, ek_bias + D, w3W, w3b, ee_bias + D);

    // ii2 = [ii ; k_emb] @ w4^T + w4_b
    gemm_dual<0><<<gbK, 256>>>(ii, k_emb, w4W, 256, w4W + 128, 256, w4b, p_ii2, n_k);

    // belong graph: CSR + mean aggregation of ii2 (shared by both layers)
    zero_deg<<<gNe, 256>>>(n_e);
    count_kernel<<<gE, 256>>>(b_dst, E);
    scan_kernel<<<1, 1024>>>(n_e);
    scatter_kernel<<<gE, 256>>>(b_src, b_dst, (const float*)nullptr, E);
    aggregate_kernel<0><<<gAgg, 256>>>(p_ii2, p_nb, n_e);

    // belong layer 0 (relu) then folded layer1+w2
    gemm_dual<1><<<gbE, 256>>>(e_emb, p_nb, ek_self, 128, ek_neigh, 128, ek_bias, p_tmp, n_e);
    gemm_dual<0><<<gbE, 256>>>(p_tmp, p_nb, p_M1, 128, p_M2, 128, p_c1, p_hiI, n_e);

    // src_com = [h_iI ; e_emb] @ w1^T + w1_b
    gemm_dual<0><<<gbE, 256>>>(p_hiI, e_emb, w1W, 256, w1W + 128, 256, w1b, p_sc, n_e);

    // collab graph: CSR + weighted mean aggregation of src_com (shared by both layers)
    zero_deg<<<gNe, 256>>>(n_e);
    count_kernel<<<gE, 256>>>(c_dst, E);
    scan_kernel<<<1, 1024>>>(n_e);
    scatter_kernel<<<gE, 256>>>(c_src, c_dst, cf_ew, E);
    aggregate_kernel<1><<<gAgg, 256>>>(p_sc, p_nc, n_e);

    // collab layer 0 (relu) then folded layer1+w3
    gemm_dual<1><<<gbE, 256>>>(e_emb, p_nc, ee_self, 128, ee_neigh, 128, ee_bias, p_tmp, n_e);
    gemm_dual<0><<<gbE, 256>>>(p_tmp, p_nc, p_M3, 128, p_M4, 128, p_c2, p_hiS, n_e);

    // final: leaky_relu([h_iI ; h_iS] @ comb^T + comb_b)
    gemm_dual<2><<<gbE, 256>>>(p_hiI, p_hiS, combW, 256, combW + 128, 256, combb, out, n_e);
}

// round 4
// speedup vs baseline: 1.3784x; 1.3784x over previous
#include <cuda_runtime.h>
#include <cuda_bf16.h>
#include <cstdint>

typedef __nv_bfloat16 bf16;
#define NK   10000
#define NE   100000
#define D    128
#define DD   (128*128)
#define EDG  1600000

// ---------------- scratch (static __device__ — no allocations allowed) ----------------
__device__ __align__(16) bf16 g_eeh[NE*D],  g_eel[NE*D];     // e_emb split
__device__ __align__(16) bf16 g_iih[NK*D],  g_iil[NK*D];     // ii split
__device__ __align__(16) bf16 g_keh[NK*D],  g_kel[NK*D];     // k_emb_weight split
__device__ __align__(16) bf16 g_ii2h[NK*D], g_ii2l[NK*D];
__device__ __align__(16) bf16 g_nbh[NE*D],  g_nbl[NE*D];
__device__ __align__(16) bf16 g_nch[NE*D],  g_ncl[NE*D];
__device__ __align__(16) bf16 g_tmph[NE*D], g_tmpl[NE*D];
__device__ __align__(16) bf16 g_hiIh[NE*D], g_hiIl[NE*D];
__device__ __align__(16) bf16 g_hiSh[NE*D], g_hiSl[NE*D];
__device__ __align__(16) bf16 g_sch[NE*D],  g_scl[NE*D];
// weights: per stage [128 N][256 K] hi/lo
__device__ __align__(16) bf16 g_Wh[7][128*256], g_Wl[7][128*256];
__device__ __align__(16) float g_M1[DD], g_M2[DD], g_M3[DD], g_M4[DD];
__device__ __align__(16) float g_c1[D], g_c2[D];
// CSR
__device__ __align__(16) int   g_deg[NE];
__device__ __align__(16) int   g_rowptr[NE + 1];
__device__ __align__(16) int   g_cursor[NE];
__device__ __align__(16) int   g_esrc[EDG];
__device__ __align__(16) float g_ew[EDG];

// ---------------- small helpers ----------------
__device__ __forceinline__ uint32_t s2u(const void* p) {
    uint32_t a;
    asm("{ .reg .u64 t; cvta.to.shared.u64 t, %1; cvt.u32.u64 %0, t; }" : "=r"(a) : "l"(p));
    return a;
}
__device__ __forceinline__ float blo(uint32_t u) {
    return __bfloat162float(__ushort_as_bfloat16((unsigned short)(u & 0xFFFF)));
}
__device__ __forceinline__ float bhi(uint32_t u) {
    return __bfloat162float(__ushort_as_bfloat16((unsigned short)(u >> 16)));
}
__device__ __forceinline__ uint32_t packbf(bf16 a, bf16 b) {
    return ((uint32_t)__bfloat16_as_ushort(b) << 16) | (uint32_t)__bfloat16_as_ushort(a);
}
__device__ __forceinline__ void ldmx4(uint32_t* r, uint32_t addr) {
    asm volatile("ldmatrix.sync.aligned.m8n8.x4.shared.b16 {%0,%1,%2,%3}, [%4];"
                 : "=r"(r[0]), "=r"(r[1]), "=r"(r[2]), "=r"(r[3]) : "r"(addr));
}
__device__ __forceinline__ void mma16816(float* c, const uint32_t* a, uint32_t b0, uint32_t b1) {
    asm volatile("mma.sync.aligned.m16n8k16.row.col.f32.bf16.bf16.f32 "
                 "{%0,%1,%2,%3}, {%4,%5,%6,%7}, {%8,%9}, {%0,%1,%2,%3};"
                 : "+f"(c[0]), "+f"(c[1]), "+f"(c[2]), "+f"(c[3])
                 : "r"(a[0]), "r"(a[1]), "r"(a[2]), "r"(a[3]), "r"(b0), "r"(b1));
}
__device__ __forceinline__ void cp16(uint32_t s, const void* g) {
    asm volatile("cp.async.cg.shared.global [%0], [%1], 16;" :: "r"(s), "l"(g));
}

// ---------------- SMEM layout (padded strides, NO xor swizzle) ----------------
// B region at 0: plane stride 67584 (hi, lo), row stride 528B (512B data + 16B pad)
// A region at 135168: buffer stride 36864 (x2), plane stride 18432 (hi, lo),
//                     row stride 144B (128B data + 16B pad)
#define SMB       0
#define B_ROW     528
#define B_PLANE   67584
#define SMA       135168
#define A_ROW     144
#define A_PLANE   18432
#define A_BUF     36864
#define SM_TOTAL  208896

// ---------------- split-bf16 GEMM on mma.sync (HMMA) ----------------
// C[M,128] = act( A1[M,128]@W[:,0:128]^T + A2[M,128]@W[:,128:256]^T + bias )
// A as hi/lo planes; W as hi/lo [128 n][256 k]. 3 passes: hh + hl + lh, fp32 acc.
template <int ACT, int OUTF32>
__global__ void __launch_bounds__(256, 1) gemm_mma(
    const bf16* __restrict__ a1h, const bf16* __restrict__ a1l,
    const bf16* __restrict__ a2h, const bf16* __restrict__ a2l,
    const bf16* __restrict__ wh,  const bf16* __restrict__ wl,
    const float* __restrict__ bias,
    bf16* __restrict__ oh, bf16* __restrict__ ol, float* __restrict__ of, int M)
{
    extern __shared__ char smem[];
    uint32_t sb = s2u(smem);
    int tid = threadIdx.x, lane = tid & 31, wid = tid >> 5;
    int wr = wid & 3, wc = wid >> 2;            // warp grid 4 (m) x 2 (n)
    int mbrow = blockIdx.x * 128;

    // ---- stage W (both planes) into smem; part of cp.async group 0 ----
    for (int i = tid; i < 8192; i += 256) {
        int pl = i >> 12, q = i & 4095;
        int n = q >> 5, g = q & 31;             // n row, 16B granule
        const bf16* W = pl ? wl : wh;
        cp16(sb + SMB + pl * B_PLANE + n * B_ROW + g * 16, W + n * 256 + g * 8);
    }
    // ---- chunk 0 of A (k 0..63 of A1) ----
    {
        int r = tid >> 3, g = tid & 7;
#pragma unroll
        for (int u = 0; u < 4; ++u) {
            int rr = r + u * 32;
            int grow = mbrow + rr;
            if (grow < M) {
                uint32_t so = sb + SMA + rr * A_ROW + g * 16;
                cp16(so,           a1h + (size_t)grow * 128 + g * 8);
                cp16(so + A_PLANE, a1l + (size_t)grow * 128 + g * 8);
            }
        }
    }
    asm volatile("cp.async.commit_group;" ::: "memory");

    float acc[2][8][4];
#pragma unroll
    for (int mi = 0; mi < 2; ++mi)
#pragma unroll
        for (int ni = 0; ni < 8; ++ni)
#pragma unroll
            for (int q = 0; q < 4; ++q) acc[mi][ni][q] = 0.f;

    // canonical ldmatrix.x4 addressing: row = lane&15, col-byte = (lane>>4)*16
    int l15 = lane & 15, lkb = (lane >> 4) * 16;
    uint32_t a_base = sb + SMA + (uint32_t)(wr * 32 + l15) * A_ROW + lkb;
    uint32_t b_base = sb + SMB + (uint32_t)(wc * 64 + l15) * B_ROW + lkb;

    for (int c = 0; c < 4; ++c) {
        if (c < 3) {   // prefetch next chunk into other buffer
            const bf16* ah = (c + 1 < 2) ? a1h : a2h;
            const bf16* al = (c + 1 < 2) ? a1l : a2l;
            int k0 = ((c + 1) & 1) * 64;
            int r = tid >> 3, g = tid & 7;
            uint32_t bufo = sb + SMA + ((c + 1) & 1) * A_BUF;
#pragma unroll
            for (int u = 0; u < 4; ++u) {
                int rr = r + u * 32;
                int grow = mbrow + rr;
                if (grow < M) {
                    uint32_t so = bufo + rr * A_ROW + g * 16;
                    cp16(so,           ah + (size_t)grow * 128 + k0 + g * 8);
                    cp16(so + A_PLANE, al + (size_t)grow * 128 + k0 + g * 8);
                }
            }
            asm volatile("cp.async.commit_group;" ::: "memory");
            asm volatile("cp.async.wait_group 1;" ::: "memory");
        } else {
            asm volatile("cp.async.wait_group 0;" ::: "memory");
        }
        __syncthreads();

        uint32_t Ab = a_base + (c & 1) * A_BUF;
        uint32_t Bb = b_base + c * 128;           // 64 k per chunk = 128 bytes
#pragma unroll
        for (int s = 0; s < 4; ++s) {             // k16 steps within chunk
            uint32_t Aks = Ab + s * 32;
            uint32_t Bks = Bb + s * 32;
            uint32_t Ah0[4], Ah1[4], Al0[4], Al1[4];
            ldmx4(Ah0, Aks);                      // rows wr*32 +  0..15 (hi)
            ldmx4(Ah1, Aks + 16 * A_ROW);         // rows wr*32 + 16..31 (hi)
            ldmx4(Al0, Aks + A_PLANE);            // lo plane
            ldmx4(Al1, Aks + A_PLANE + 16 * A_ROW);
            uint32_t Bh[4][4], Bl[4][4];
#pragma unroll
            for (int nb = 0; nb < 4; ++nb) ldmx4(Bh[nb], Bks + nb * (16 * B_ROW));
#pragma unroll
            for (int nb = 0; nb < 4; ++nb) ldmx4(Bl[nb], Bks + B_PLANE + nb * (16 * B_ROW));
            // pass 1: Ah * Bh
#pragma unroll
            for (int ni = 0; ni < 8; ++ni) {
                int nb = ni >> 1, hb = ni & 1;
                mma16816(acc[0][ni], Ah0, Bh[nb][hb], Bh[nb][2 + hb]);
                mma16816(acc[1][ni], Ah1, Bh[nb][hb], Bh[nb][2 + hb]);
            }
            // pass 2: Ah * Bl
#pragma unroll
            for (int ni = 0; ni < 8; ++ni) {
                int nb = ni >> 1, hb = ni & 1;
                mma16816(acc[0][ni], Ah0, Bl[nb][hb], Bl[nb][2 + hb]);
                mma16816(acc[1][ni], Ah1, Bl[nb][hb], Bl[nb][2 + hb]);
            }
            // pass 3: Al * Bh
#pragma unroll
            for (int ni = 0; ni < 8; ++ni) {
                int nb = ni >> 1, hb = ni & 1;
                mma16816(acc[0][ni], Al0, Bh[nb][hb], Bh[nb][2 + hb]);
                mma16816(acc[1][ni], Al1, Bh[nb][hb], Bh[nb][2 + hb]);
            }
        }
        __syncthreads();
    }

    // ---- epilogue: bias + act + (re-split bf16 | fp32) stores ----
    int quad = lane >> 2, tq = lane & 3;
#pragma unroll
    for (int ni = 0; ni < 8; ++ni) {
        int cbase = wc * 64 + ni * 8 + tq * 2;
        float bv0 = __ldg(bias + cbase), bv1 = __ldg(bias + cbase + 1);
#pragma unroll
        for (int mi = 0; mi < 2; ++mi) {
#pragma unroll
            for (int h = 0; h < 2; ++h) {
                int grow = mbrow + wr * 32 + mi * 16 + quad + h * 8;
                if (grow >= M) continue;
                float x0 = acc[mi][ni][2 * h + 0] + bv0;
                float x1 = acc[mi][ni][2 * h + 1] + bv1;
                if (ACT == 1) { x0 = fmaxf(x0, 0.f); x1 = fmaxf(x1, 0.f); }
                if (ACT == 2) { x0 = (x0 >= 0.f) ? x0 : 0.2f * x0;
                                x1 = (x1 >= 0.f) ? x1 : 0.2f * x1; }
                if (OUTF32) {
                    *(float2*)(of + (size_t)grow * 128 + cbase) = make_float2(x0, x1);
                } else {
                    bf16 h0 = __float2bfloat16(x0), h1 = __float2bfloat16(x1);
                    bf16 l0 = __float2bfloat16(x0 - __bfloat162float(h0));
                    bf16 l1 = __float2bfloat16(x1 - __bfloat162float(h1));
                    *(uint32_t*)(oh + (size_t)grow * 128 + cbase) = packbf(h0, h1);
                    *(uint32_t*)(ol + (size_t)grow * 128 + cbase) = packbf(l0, l1);
                }
            }
        }
    }
}

// ---------------- weight folding (fp32) ----------------
__global__ void fold_mats(const float* __restrict__ w2, const float* __restrict__ ekS1,
                          const float* __restrict__ ekN1, const float* __restrict__ w3,
                          const float* __restrict__ eeS1, const float* __restrict__ eeN1) {
    int mat = blockIdx.y;
    const float* A; const float* B; float* O;
    if (mat == 0)      { A = w2; B = ekS1; O = g_M1; }
    else if (mat == 1) { A = w2; B = ekN1; O = g_M2; }
    else if (mat == 2) { A = w3; B = eeS1; O = g_M3; }
    else               { A = w3; B = eeN1; O = g_M4; }
    int idx = blockIdx.x * blockDim.x + threadIdx.x;
    int n = idx >> 7, k = idx & 127;
    float acc = 0.f;
#pragma unroll 8
    for (int j = 0; j < 128; ++j)
        acc += A[n * 128 + j] * B[j * 128 + k];
    O[idx] = acc;
}

__global__ void fold_bias(const float* __restrict__ w2, const float* __restrict__ w2b,
                          const float* __restrict__ ekb1, const float* __restrict__ w3,
                          const float* __restrict__ w3b, const float* __restrict__ eeb1) {
    int t = threadIdx.x;
    float a = 0.f, b = 0.f;
#pragma unroll 8
    for (int j = 0; j < 128; ++j) {
        a += w2[t * 128 + j] * ekb1[j];
        b += w3[t * 128 + j] * eeb1[j];
    }
    g_c1[t] = a + w2b[t];
    g_c2[t] = b + w3b[t];
}

// ---------------- conversions ----------------
__global__ void conv_w(const float* __restrict__ a, const float* __restrict__ b,
                       bf16* __restrict__ wh, bf16* __restrict__ wl) {
    int i = blockIdx.x * blockDim.x + threadIdx.x;
    if (i >= 32768) return;
    int n = i >> 8, k = i & 255;
    float v = b ? (k < 128 ? a[n * 128 + k] : b[n * 128 + (k - 128)]) : a[i];
    bf16 h = __float2bfloat16(v);
    wh[i] = h;
    wl[i] = __float2bfloat16(v - __bfloat162float(h));
}

__global__ void conv_act(const float* __restrict__ x, bf16* __restrict__ h,
                         bf16* __restrict__ l, int n) {
    int i = blockIdx.x * blockDim.x + threadIdx.x;
    if (i >= n) return;
    float v = x[i];
    bf16 hb = __float2bfloat16(v);
    h[i] = hb;
    l[i] = __float2bfloat16(v - __bfloat162float(hb));
}

// ---------------- CSR build ----------------
__global__ void zero_deg(int n) {
    int i = blockIdx.x * blockDim.x + threadIdx.x;
    if (i < n) g_deg[i] = 0;
}
__global__ void count_kernel(const int* __restrict__ dst, int E) {
    int i = blockIdx.x * blockDim.x + threadIdx.x;
    if (i < E) atomicAdd(&g_deg[dst[i]], 1);
}
__global__ void scan_kernel(int n) {
    __shared__ int wsum[32];
    int tid = threadIdx.x, lane = tid & 31, wid = tid >> 5;
    int carry = 0;
    for (int base = 0; base < n; base += 4096) {
        int idx = base + tid * 4;
        int v0 = (idx + 0 < n) ? g_deg[idx + 0] : 0;
        int v1 = (idx + 1 < n) ? g_deg[idx + 1] : 0;
        int v2 = (idx + 2 < n) ? g_deg[idx + 2] : 0;
        int v3 = (idx + 3 < n) ? g_deg[idx + 3] : 0;
        int t1 = v0, t2 = v0 + v1, t3 = t2 + v2, ts = t3 + v3;
        int inc = ts;
#pragma unroll
        for (int o = 1; o < 32; o <<= 1) {
            int x = __shfl_up_sync(0xFFFFFFFFu, inc, o);
            if (lane >= o) inc += x;
        }
        if (lane == 31) wsum[wid] = inc;
        __syncthreads();
        if (wid == 0) {
            int si = wsum[lane];
#pragma unroll
            for (int o = 1; o < 32; o <<= 1) {
                int x = __shfl_up_sync(0xFFFFFFFFu, si, o);
                if (lane >= o) si += x;
            }
            wsum[lane] = si;
        }
        __syncthreads();
        int wexc = wid ? wsum[wid - 1] : 0;
        int texc = carry + wexc + inc - ts;
        if (idx + 0 < n) { g_rowptr[idx + 0] = texc;      g_cursor[idx + 0] = texc; }
        if (idx + 1 < n) { g_rowptr[idx + 1] = texc + t1; g_cursor[idx + 1] = texc + t1; }
        if (idx + 2 < n) { g_rowptr[idx + 2] = texc + t2; g_cursor[idx + 2] = texc + t2; }
        if (idx + 3 < n) { g_rowptr[idx + 3] = texc + t3; g_cursor[idx + 3] = texc + t3; }
        carry += wsum[31];
        __syncthreads();
    }
    if (tid == 0) g_rowptr[n] = carry;
}
__global__ void scatter_kernel(const int* __restrict__ src, const int* __restrict__ dst,
                               const float* __restrict__ ew, int E) {
    int i = blockIdx.x * blockDim.x + threadIdx.x;
    if (i >= E) return;
    int d = dst[i];
    int pos = atomicAdd(&g_cursor[d], 1);
    g_esrc[pos] = src[i];
    if (ew) g_ew[pos] = ew[i];
}

// ---------------- mean aggregation on hi/lo planes: warp per destination ----------------
template <int WEIGHTED>
__global__ void aggregate_kernel(const bf16* __restrict__ sh, const bf16* __restrict__ sl,
                                 bf16* __restrict__ oh, bf16* __restrict__ ol, int n) {
    int gw = (blockIdx.x * blockDim.x + threadIdx.x) >> 5;
    int lane = threadIdx.x & 31;
    if (gw >= n) return;
    int s0 = g_rowptr[gw], s1 = g_rowptr[gw + 1];
    float a0 = 0.f, a1 = 0.f, a2 = 0.f, a3 = 0.f;
    for (int j = s0; j < s1; ++j) {
        int sidx = g_esrc[j];
        uint2 uh = *(const uint2*)(sh + (size_t)sidx * D + lane * 4);
        uint2 ul = *(const uint2*)(sl + (size_t)sidx * D + lane * 4);
        float w = WEIGHTED ? g_ew[j] : 1.0f;
        a0 += (blo(uh.x) + blo(ul.x)) * w;
        a1 += (bhi(uh.x) + bhi(ul.x)) * w;
        a2 += (blo(uh.y) + blo(ul.y)) * w;
        a3 += (bhi(uh.y) + bhi(ul.y)) * w;
    }
    float inv = 1.0f / fmaxf((float)(s1 - s0), 1.0f);
    a0 *= inv; a1 *= inv; a2 *= inv; a3 *= inv;
    bf16 h0 = __float2bfloat16(a0), h1 = __float2bfloat16(a1);
    bf16 h2 = __float2bfloat16(a2), h3 = __float2bfloat16(a3);
    bf16 l0 = __float2bfloat16(a0 - __bfloat162float(h0));
    bf16 l1 = __float2bfloat16(a1 - __bfloat162float(h1));
    bf16 l2 = __float2bfloat16(a2 - __bfloat162float(h2));
    bf16 l3 = __float2bfloat16(a3 - __bfloat162float(h3));
    *(uint2*)(oh + (size_t)gw * D + lane * 4) = make_uint2(packbf(h0, h1), packbf(h2, h3));
    *(uint2*)(ol + (size_t)gw * D + lane * 4) = make_uint2(packbf(l0, l1), packbf(l2, l3));
}

// ---------------- launch ----------------
extern "C" void kernel_launch(void* const* d_in, const int* in_sizes, int n_in,
                              void* d_out, int out_size) {
    const float* ii      = (const float*)d_in[0];
    const float* e_emb   = (const float*)d_in[1];
    const float* k_emb   = (const float*)d_in[2];
    const float* cf_ew   = (const float*)d_in[3];
    const int*   b_src   = (const int*)d_in[4];
    const int*   b_dst   = (const int*)d_in[5];
    const int*   c_src   = (const int*)d_in[6];
    const int*   c_dst   = (const int*)d_in[7];
    const float* ek_self = (const float*)d_in[8];
    const float* ek_neigh= (const float*)d_in[9];
    const float* ek_bias = (const float*)d_in[10];
    const float* ee_self = (const float*)d_in[11];
    const float* ee_neigh= (const float*)d_in[12];
    const float* ee_bias = (const float*)d_in[13];
    const float* w1W = (const float*)d_in[14];
    const float* w1b = (const float*)d_in[15];
    const float* w2W = (const float*)d_in[16];
    const float* w2b = (const float*)d_in[17];
    const float* w3W = (const float*)d_in[18];
    const float* w3b = (const float*)d_in[19];
    const float* w4W = (const float*)d_in[20];
    const float* w4b = (const float*)d_in[21];
    const float* combW = (const float*)d_in[22];
    const float* combb = (const float*)d_in[23];
    float* out = (float*)d_out;

    int n_k = in_sizes[0] / D;
    int n_e = in_sizes[1] / D;
    int E   = in_sizes[4];

    bf16 *eeh, *eel, *iih, *iil, *keh, *kel, *ii2h, *ii2l;
    bf16 *nbh, *nbl, *nch, *ncl, *tmph, *tmpl, *hiIh, *hiIl, *hiSh, *hiSl, *sch, *scl;
    bf16 *Wh, *Wl;
    float *p_M1, *p_M2, *p_M3, *p_M4, *p_c1, *p_c2;
    cudaGetSymbolAddress((void**)&eeh, g_eeh);   cudaGetSymbolAddress((void**)&eel, g_eel);
    cudaGetSymbolAddress((void**)&iih, g_iih);   cudaGetSymbolAddress((void**)&iil, g_iil);
    cudaGetSymbolAddress((void**)&keh, g_keh);   cudaGetSymbolAddress((void**)&kel, g_kel);
    cudaGetSymbolAddress((void**)&ii2h, g_ii2h); cudaGetSymbolAddress((void**)&ii2l, g_ii2l);
    cudaGetSymbolAddress((void**)&nbh, g_nbh);   cudaGetSymbolAddress((void**)&nbl, g_nbl);
    cudaGetSymbolAddress((void**)&nch, g_nch);   cudaGetSymbolAddress((void**)&ncl, g_ncl);
    cudaGetSymbolAddress((void**)&tmph, g_tmph); cudaGetSymbolAddress((void**)&tmpl, g_tmpl);
    cudaGetSymbolAddress((void**)&hiIh, g_hiIh); cudaGetSymbolAddress((void**)&hiIl, g_hiIl);
    cudaGetSymbolAddress((void**)&hiSh, g_hiSh); cudaGetSymbolAddress((void**)&hiSl, g_hiSl);
    cudaGetSymbolAddress((void**)&sch, g_sch);   cudaGetSymbolAddress((void**)&scl, g_scl);
    cudaGetSymbolAddress((void**)&Wh, g_Wh);     cudaGetSymbolAddress((void**)&Wl, g_Wl);
    cudaGetSymbolAddress((void**)&p_M1, g_M1);   cudaGetSymbolAddress((void**)&p_M2, g_M2);
    cudaGetSymbolAddress((void**)&p_M3, g_M3);   cudaGetSymbolAddress((void**)&p_M4, g_M4);
    cudaGetSymbolAddress((void**)&p_c1, g_c1);   cudaGetSymbolAddress((void**)&p_c2, g_c2);

    cudaFuncSetAttribute(gemm_mma<0, 0>, cudaFuncAttributeMaxDynamicSharedMemorySize, SM_TOTAL);
    cudaFuncSetAttribute(gemm_mma<1, 0>, cudaFuncAttributeMaxDynamicSharedMemorySize, SM_TOTAL);
    cudaFuncSetAttribute(gemm_mma<2, 1>, cudaFuncAttributeMaxDynamicSharedMemorySize, SM_TOTAL);

    int gE  = (E + 255) / 256;
    int gNe = (n_e + 255) / 256;
    int gAgg = (n_e * 32 + 255) / 256;
    int gbK = (n_k + 127) / 128;
    int gbE = (n_e + 127) / 128;

    // ---- prep: fold layer-1 weights, split-convert all weights & input activations ----
    fold_mats<<<dim3(64, 4), 256>>>(w2W, ek_self + DD, ek_neigh + DD,
                                    w3W, ee_self + DD, ee_neigh + DD);
    fold_bias<<<1, 128>>>(w2W, w2b, ek_bias + D, w3W, w3b, ee_bias + D);
    conv_w<<<128, 256>>>(w4W, nullptr,      Wh + 0*32768, Wl + 0*32768);
    conv_w<<<128, 256>>>(ek_self, ek_neigh, Wh + 1*32768, Wl + 1*32768);
    conv_w<<<128, 256>>>(p_M1, p_M2,        Wh + 2*32768, Wl + 2*32768);
    conv_w<<<128, 256>>>(w1W, nullptr,      Wh + 3*32768, Wl + 3*32768);
    conv_w<<<128, 256>>>(ee_self, ee_neigh, Wh + 4*32768, Wl + 4*32768);
    conv_w<<<128, 256>>>(p_M3, p_M4,        Wh + 5*32768, Wl + 5*32768);
    conv_w<<<128, 256>>>(combW, nullptr,    Wh + 6*32768, Wl + 6*32768);
    conv_act<<<(n_k * D + 255) / 256, 256>>>(ii,    iih, iil, n_k * D);
    conv_act<<<(n_k * D + 255) / 256, 256>>>(k_emb, keh, kel, n_k * D);
    conv_act<<<(n_e * D + 255) / 256, 256>>>(e_emb, eeh, eel, n_e * D);

    // ---- ii2 = [ii ; k_emb] @ w4^T + w4_b ----
    gemm_mma<0, 0><<<gbK, 256, SM_TOTAL>>>(iih, iil, keh, kel,
                                           Wh + 0*32768, Wl + 0*32768, w4b,
                                           ii2h, ii2l, nullptr, n_k);

    // ---- belong graph: CSR + mean aggregation of ii2 (shared by both layers) ----
    zero_deg<<<gNe, 256>>>(n_e);
    count_kernel<<<gE, 256>>>(b_dst, E);
    scan_kernel<<<1, 1024>>>(n_e);
    scatter_kernel<<<gE, 256>>>(b_src, b_dst, (const float*)nullptr, E);
    aggregate_kernel<0><<<gAgg, 256>>>(ii2h, ii2l, nbh, nbl, n_e);

    // ---- belong layer 0 (relu), then folded layer1+w2 ----
    gemm_mma<1, 0><<<gbE, 256, SM_TOTAL>>>(eeh, eel, nbh, nbl,
                                           Wh + 1*32768, Wl + 1*32768, ek_bias,
                                           tmph, tmpl, nullptr, n_e);
    gemm_mma<0, 0><<<gbE, 256, SM_TOTAL>>>(tmph, tmpl, nbh, nbl,
                                           Wh + 2*32768, Wl + 2*32768, p_c1,
                                           hiIh, hiIl, nullptr, n_e);

    // ---- src_com = [h_iI ; e_emb] @ w1^T + w1_b ----
    gemm_mma<0, 0><<<gbE, 256, SM_TOTAL>>>(hiIh, hiIl, eeh, eel,
                                           Wh + 3*32768, Wl + 3*32768, w1b,
                                           sch, scl, nullptr, n_e);

    // ---- collab graph: CSR + weighted mean aggregation of src_com ----
    zero_deg<<<gNe, 256>>>(n_e);
    count_kernel<<<gE, 256>>>(c_dst, E);
    scan_kernel<<<1, 1024>>>(n_e);
    scatter_kernel<<<gE, 256>>>(c_src, c_dst, cf_ew, E);
    aggregate_kernel<1><<<gAgg, 256>>>(sch, scl, nch, ncl, n_e);

    // ---- collab layer 0 (relu), then folded layer1+w3 ----
    gemm_mma<1, 0><<<gbE, 256, SM_TOTAL>>>(eeh, eel, nch, ncl,
                                           Wh + 4*32768, Wl + 4*32768, ee_bias,
                                           tmph, tmpl, nullptr, n_e);
    gemm_mma<0, 0><<<gbE, 256, SM_TOTAL>>>(tmph, tmpl, nch, ncl,
                                           Wh + 5*32768, Wl + 5*32768, p_c2,
                                           hiSh, hiSl, nullptr, n_e);

    // ---- final: leaky_relu([h_iI ; h_iS] @ comb^T + comb_b) -> fp32 out ----
    gemm_mma<2, 1><<<gbE, 256, SM_TOTAL>>>(hiIh, hiIl, hiSh, hiSl,
                                           Wh + 6*32768, Wl + 6*32768, combb,
                                           nullptr, nullptr, out, n_e);
}

// round 5
// speedup vs baseline: 1.7509x; 1.2703x over previous
#include <cuda_runtime.h>
#include <cuda_bf16.h>
#include <cstdint>

typedef __nv_bfloat16 bf16;
#define NK   10000
#define NE   100000
#define D    128
#define DD   (128*128)
#define EDG  1600000

// ---------------- scratch (static __device__ — no allocations allowed) ----------------
__device__ __align__(16) bf16 g_eeh[NE*D],  g_eel[NE*D];
__device__ __align__(16) bf16 g_iih[NK*D],  g_iil[NK*D];
__device__ __align__(16) bf16 g_keh[NK*D],  g_kel[NK*D];
__device__ __align__(16) bf16 g_ii2h[NK*D], g_ii2l[NK*D];
__device__ __align__(16) bf16 g_nbh[NE*D],  g_nbl[NE*D];
__device__ __align__(16) bf16 g_nch[NE*D],  g_ncl[NE*D];
__device__ __align__(16) bf16 g_tmph[NE*D], g_tmpl[NE*D];
__device__ __align__(16) bf16 g_hiIh[NE*D], g_hiIl[NE*D];
__device__ __align__(16) bf16 g_hiSh[NE*D], g_hiSl[NE*D];
__device__ __align__(16) bf16 g_sch[NE*D],  g_scl[NE*D];
__device__ __align__(16) bf16 g_Wh[7][128*256], g_Wl[7][128*256];
__device__ __align__(16) float g_M1[DD], g_M2[DD], g_M3[DD], g_M4[DD];
__device__ __align__(16) float g_c1[D], g_c2[D];
// CSR (per graph: B = belong, C = collab)
__device__ __align__(16) int   g_degB[NE], g_degC[NE];
__device__ __align__(16) int   g_rpB[NE+1], g_rpC[NE+1];
__device__ __align__(16) int   g_curB[NE], g_curC[NE];
__device__ __align__(16) int   g_esrcB[EDG], g_esrcC[EDG];
__device__ __align__(16) float g_ewC[EDG];
__device__ __align__(16) int   g_part[2*128];

// ---------------- small helpers ----------------
__device__ __forceinline__ uint32_t s2u(const void* p) {
    uint32_t a;
    asm("{ .reg .u64 t; cvta.to.shared.u64 t, %1; cvt.u32.u64 %0, t; }" : "=r"(a) : "l"(p));
    return a;
}
__device__ __forceinline__ float blo(uint32_t u) {
    return __bfloat162float(__ushort_as_bfloat16((unsigned short)(u & 0xFFFF)));
}
__device__ __forceinline__ float bhi(uint32_t u) {
    return __bfloat162float(__ushort_as_bfloat16((unsigned short)(u >> 16)));
}
__device__ __forceinline__ uint32_t packbf(bf16 a, bf16 b) {
    return ((uint32_t)__bfloat16_as_ushort(b) << 16) | (uint32_t)__bfloat16_as_ushort(a);
}
__device__ __forceinline__ void ldmx4(uint32_t* r, uint32_t addr) {
    asm volatile("ldmatrix.sync.aligned.m8n8.x4.shared.b16 {%0,%1,%2,%3}, [%4];"
                 : "=r"(r[0]), "=r"(r[1]), "=r"(r[2]), "=r"(r[3]) : "r"(addr));
}
__device__ __forceinline__ void mma16816(float* c, const uint32_t* a, uint32_t b0, uint32_t b1) {
    asm volatile("mma.sync.aligned.m16n8k16.row.col.f32.bf16.bf16.f32 "
                 "{%0,%1,%2,%3}, {%4,%5,%6,%7}, {%8,%9}, {%0,%1,%2,%3};"
                 : "+f"(c[0]), "+f"(c[1]), "+f"(c[2]), "+f"(c[3])
                 : "r"(a[0]), "r"(a[1]), "r"(a[2]), "r"(a[3]), "r"(b0), "r"(b1));
}
__device__ __forceinline__ void cp16(uint32_t s, const void* g) {
    asm volatile("cp.async.cg.shared.global [%0], [%1], 16;" :: "r"(s), "l"(g));
}

// ---------------- SMEM layout (padded strides, linear addressing) ----------------
// A buffers first: buf {hi plane, lo plane}, row stride 144B. Then B buffers same shape.
#define A_ROW    144
#define A_PLANE  18432            // 128*144
#define A_BUF    36864            // 2 planes
#define SMB_OFF  73728            // 2 A buffers
#define B_ROW    144
#define B_PLANE  18432
#define B_BUF    36864
#define SM_TOTAL 147456           // + B buffers (2)
#define C_ROW    544              // epilogue fp32 tile row stride (reuses smem from 0)

// ---------------- split-bf16 GEMM on mma.sync (HMMA), k-chunk pipelined ----------------
// C[M,128] = act( A1[M,128]@W[:,0:128]^T + A2[M,128]@W[:,128:256]^T + bias )
// 4 chunks of k=64 (A1:0-127, A2:128-255). 3 passes: hh + hl + lh, fp32 acc.
template <int ACT, int OUTF32>
__global__ void __launch_bounds__(256, 1) gemm_mma(
    const bf16* __restrict__ a1h, const bf16* __restrict__ a1l,
    const bf16* __restrict__ a2h, const bf16* __restrict__ a2l,
    const bf16* __restrict__ wh,  const bf16* __restrict__ wl,
    const float* __restrict__ bias,
    bf16* __restrict__ oh, bf16* __restrict__ ol, float* __restrict__ of, int M)
{
    extern __shared__ char smem[];
    uint32_t sb = s2u(smem);
    int tid = threadIdx.x, lane = tid & 31, wid = tid >> 5;
    int wr = wid & 3, wc = wid >> 2;            // warp grid 4 (m) x 2 (n)
    int mbrow = blockIdx.x * 128;

    // chunk loader: A chunk (128r x 64k, 2 planes) + B chunk (128n x 64k, 2 planes)
    auto load_chunk = [&](int c, int buf) {
        const bf16* ah = (c < 2) ? a1h : a2h;
        const bf16* al = (c < 2) ? a1l : a2l;
        int k0 = (c & 1) * 64;
#pragma unroll
        for (int u = 0; u < 8; ++u) {           // A: 2048 16B granules / 256 thr
            int i = u * 256 + tid;
            int pl = i >> 10, row = (i >> 3) & 127, g = i & 7;
            int grow = mbrow + row;
            if (grow < M)
                cp16(sb + buf * A_BUF + pl * A_PLANE + row * A_ROW + g * 16,
                     (pl ? al : ah) + (size_t)grow * 128 + k0 + g * 8);
        }
#pragma unroll
        for (int u = 0; u < 8; ++u) {           // B: 2048 granules
            int i = u * 256 + tid;
            int pl = i >> 10, n = (i >> 3) & 127, g = i & 7;
            cp16(sb + SMB_OFF + buf * B_BUF + pl * B_PLANE + n * B_ROW + g * 16,
                 (pl ? wl : wh) + n * 256 + c * 64 + g * 8);
        }
        asm volatile("cp.async.commit_group;" ::: "memory");
    };

    load_chunk(0, 0);
    load_chunk(1, 1);

    float acc[2][8][4];
#pragma unroll
    for (int mi = 0; mi < 2; ++mi)
#pragma unroll
        for (int ni = 0; ni < 8; ++ni)
#pragma unroll
            for (int q = 0; q < 4; ++q) acc[mi][ni][q] = 0.f;

    int l15 = lane & 15, lkb = (lane >> 4) * 16;

    for (int c = 0; c < 4; ++c) {
        if (c < 3) asm volatile("cp.async.wait_group 1;" ::: "memory");
        else       asm volatile("cp.async.wait_group 0;" ::: "memory");
        __syncthreads();

        int buf = c & 1;
        uint32_t Ab = sb + buf * A_BUF + (uint32_t)(wr * 32 + l15) * A_ROW + lkb;
        uint32_t Bb = sb + SMB_OFF + buf * B_BUF + (uint32_t)(wc * 64 + l15) * B_ROW + lkb;
#pragma unroll
        for (int s = 0; s < 4; ++s) {
            uint32_t Aks = Ab + s * 32;
            uint32_t Bks = Bb + s * 32;
            uint32_t Ah0[4], Ah1[4], Al0[4], Al1[4];
            ldmx4(Ah0, Aks);
            ldmx4(Ah1, Aks + 16 * A_ROW);
            ldmx4(Al0, Aks + A_PLANE);
            ldmx4(Al1, Aks + A_PLANE + 16 * A_ROW);
            uint32_t Bh[4][4], Bl[4][4];
#pragma unroll
            for (int nb = 0; nb < 4; ++nb) ldmx4(Bh[nb], Bks + nb * (16 * B_ROW));
#pragma unroll
            for (int nb = 0; nb < 4; ++nb) ldmx4(Bl[nb], Bks + B_PLANE + nb * (16 * B_ROW));
#pragma unroll
            for (int ni = 0; ni < 8; ++ni) {
                int nb = ni >> 1, hb = ni & 1;
                mma16816(acc[0][ni], Ah0, Bh[nb][hb], Bh[nb][2 + hb]);
                mma16816(acc[1][ni], Ah1, Bh[nb][hb], Bh[nb][2 + hb]);
            }
#pragma unroll
            for (int ni = 0; ni < 8; ++ni) {
                int nb = ni >> 1, hb = ni & 1;
                mma16816(acc[0][ni], Ah0, Bl[nb][hb], Bl[nb][2 + hb]);
                mma16816(acc[1][ni], Ah1, Bl[nb][hb], Bl[nb][2 + hb]);
            }
#pragma unroll
            for (int ni = 0; ni < 8; ++ni) {
                int nb = ni >> 1, hb = ni & 1;
                mma16816(acc[0][ni], Al0, Bh[nb][hb], Bh[nb][2 + hb]);
                mma16816(acc[1][ni], Al1, Bh[nb][hb], Bh[nb][2 + hb]);
            }
        }
        __syncthreads();
        if (c + 2 < 4) load_chunk(c + 2, buf);
    }

    // ---- epilogue: acc -> smem fp32 Ctile (bias+act applied) -> coalesced stores ----
    int quad = lane >> 2, tq = lane & 3;
#pragma unroll
    for (int ni = 0; ni < 8; ++ni) {
        int cbase = wc * 64 + ni * 8 + tq * 2;
        float bv0 = __ldg(bias + cbase), bv1 = __ldg(bias + cbase + 1);
#pragma unroll
        for (int mi = 0; mi < 2; ++mi) {
#pragma unroll
            for (int h = 0; h < 2; ++h) {
                int row = wr * 32 + mi * 16 + quad + h * 8;
                float x0 = acc[mi][ni][2 * h + 0] + bv0;
                float x1 = acc[mi][ni][2 * h + 1] + bv1;
                if (ACT == 1) { x0 = fmaxf(x0, 0.f); x1 = fmaxf(x1, 0.f); }
                if (ACT == 2) { x0 = (x0 >= 0.f) ? x0 : 0.2f * x0;
                                x1 = (x1 >= 0.f) ? x1 : 0.2f * x1; }
                *(float2*)(smem + row * C_ROW + cbase * 4) = make_float2(x0, x1);
            }
        }
    }
    __syncthreads();

    int row2 = lane >> 4, colg = lane & 15;     // warp writes 2 contiguous rows / iter
#pragma unroll
    for (int it = 0; it < 8; ++it) {
        int r = wid * 16 + it * 2 + row2;
        int grow = mbrow + r;
        if (grow >= M) continue;
        float4 v0 = *(float4*)(smem + r * C_ROW + colg * 32);
        float4 v1 = *(float4*)(smem + r * C_ROW + colg * 32 + 16);
        if (OUTF32) {
            *(float4*)(of + (size_t)grow * 128 + colg * 8)     = v0;
            *(float4*)(of + (size_t)grow * 128 + colg * 8 + 4) = v1;
        } else {
            float xs[8] = { v0.x, v0.y, v0.z, v0.w, v1.x, v1.y, v1.z, v1.w };
            uint32_t hp[4], lp[4];
#pragma unroll
            for (int q = 0; q < 4; ++q) {
                bf16 h0 = __float2bfloat16(xs[2*q]),   h1 = __float2bfloat16(xs[2*q+1]);
                bf16 l0 = __float2bfloat16(xs[2*q]   - __bfloat162float(h0));
                bf16 l1 = __float2bfloat16(xs[2*q+1] - __bfloat162float(h1));
                hp[q] = packbf(h0, h1);
                lp[q] = packbf(l0, l1);
            }
            *(uint4*)(oh + (size_t)grow * 128 + colg * 8) = make_uint4(hp[0], hp[1], hp[2], hp[3]);
            *(uint4*)(ol + (size_t)grow * 128 + colg * 8) = make_uint4(lp[0], lp[1], lp[2], lp[3]);
        }
    }
}

// ---------------- prep1: conv_act (ee/ii/ke) + fold_mats + fold_bias ----------------
__global__ void prep1(const float* __restrict__ e_emb, const float* __restrict__ ii,
                      const float* __restrict__ k_emb,
                      const float* __restrict__ w2W, const float* __restrict__ w2b,
                      const float* __restrict__ w3W, const float* __restrict__ w3b,
                      const float* __restrict__ ekS1, const float* __restrict__ ekN1,
                      const float* __restrict__ eeS1, const float* __restrict__ eeN1,
                      const float* __restrict__ ekb1, const float* __restrict__ eeb1) {
    int bid = blockIdx.x, tid = threadIdx.x;
    if (bid < 50000) {                          // e_emb split
        int i = bid * 256 + tid;
        float v = e_emb[i];
        bf16 h = __float2bfloat16(v);
        g_eeh[i] = h; g_eel[i] = __float2bfloat16(v - __bfloat162float(h));
    } else if (bid < 55000) {                   // ii split
        int i = (bid - 50000) * 256 + tid;
        float v = ii[i];
        bf16 h = __float2bfloat16(v);
        g_iih[i] = h; g_iil[i] = __float2bfloat16(v - __bfloat162float(h));
    } else if (bid < 60000) {                   // k_emb split
        int i = (bid - 55000) * 256 + tid;
        float v = k_emb[i];
        bf16 h = __float2bfloat16(v);
        g_keh[i] = h; g_kel[i] = __float2bfloat16(v - __bfloat162float(h));
    } else if (bid < 60256) {                   // fold_mats: M = A @ B
        int lb = bid - 60000;
        int mat = lb >> 6;
        int idx = (lb & 63) * 256 + tid;
        const float* A = (mat < 2) ? w2W : w3W;
        const float* B = (mat == 0) ? ekS1 : (mat == 1) ? ekN1 : (mat == 2) ? eeS1 : eeN1;
        float* O = (mat == 0) ? g_M1 : (mat == 1) ? g_M2 : (mat == 2) ? g_M3 : g_M4;
        int n = idx >> 7, k = idx & 127;
        float acc = 0.f;
#pragma unroll 8
        for (int j = 0; j < 128; ++j)
            acc += A[n * 128 + j] * B[j * 128 + k];
        O[idx] = acc;
    } else {                                    // fold_bias
        int t = tid;
        if (t < 128) {
            float a = 0.f, b = 0.f;
#pragma unroll 8
            for (int j = 0; j < 128; ++j) {
                a += w2W[t * 128 + j] * ekb1[j];
                b += w3W[t * 128 + j] * eeb1[j];
            }
            g_c1[t] = a + w2b[t];
            g_c2[t] = b + w3b[t];
        }
    }
}

// ---------------- prep2: split-convert all 7 stage weight matrices ----------------
__global__ void prep2(const float* __restrict__ w4W, const float* __restrict__ ek_self,
                      const float* __restrict__ ek_neigh, const float* __restrict__ w1W,
                      const float* __restrict__ ee_self, const float* __restrict__ ee_neigh,
                      const float* __restrict__ combW) {
    int bid = blockIdx.x;
    int stage = bid >> 7;
    int idx = (bid & 127) * 256 + threadIdx.x;
    const float* a; const float* b;
    switch (stage) {
        case 0: a = w4W;     b = nullptr;   break;
        case 1: a = ek_self; b = ek_neigh;  break;
        case 2: a = g_M1;    b = g_M2;      break;
        case 3: a = w1W;     b = nullptr;   break;
        case 4: a = ee_self; b = ee_neigh;  break;
        case 5: a = g_M3;    b = g_M4;      break;
        default: a = combW;  b = nullptr;   break;
    }
    int n = idx >> 8, k = idx & 255;
    float v = b ? (k < 128 ? a[n * 128 + k] : b[n * 128 + (k - 128)]) : a[idx];
    bf16 h = __float2bfloat16(v);
    g_Wh[stage][idx] = h;
    g_Wl[stage][idx] = __float2bfloat16(v - __bfloat162float(h));
}

// ---------------- CSR build (both graphs via gridDim.y) ----------------
__global__ void zero_both() {
    int i = blockIdx.x * blockDim.x + threadIdx.x;
    if (i < NE) (blockIdx.y ? g_degC : g_degB)[i] = 0;
}
__global__ void count_both(const int* __restrict__ b_dst, const int* __restrict__ c_dst, int E) {
    int i = blockIdx.x * blockDim.x + threadIdx.x;
    if (i >= E) return;
    if (blockIdx.y) atomicAdd(&g_degC[c_dst[i]], 1);
    else            atomicAdd(&g_degB[b_dst[i]], 1);
}
// phase A: per-block exclusive scan of deg -> rowptr (partial), block sums -> g_part
__global__ void scanA() {
    __shared__ int ws[32];
    int g = blockIdx.y, tid = threadIdx.x, lane = tid & 31, wid = tid >> 5;
    int* deg = g ? g_degC : g_degB;
    int* rp  = g ? g_rpC  : g_rpB;
    int i = blockIdx.x * 1024 + tid;
    int v = (i < NE) ? deg[i] : 0;
    int inc = v;
#pragma unroll
    for (int o = 1; o < 32; o <<= 1) {
        int x = __shfl_up_sync(0xFFFFFFFFu, inc, o);
        if (lane >= o) inc += x;
    }
    if (lane == 31) ws[wid] = inc;
    __syncthreads();
    if (wid == 0) {
        int s = ws[lane];
#pragma unroll
        for (int o = 1; o < 32; o <<= 1) {
            int x = __shfl_up_sync(0xFFFFFFFFu, s, o);
            if (lane >= o) s += x;
        }
        ws[lane] = s;
    }
    __syncthreads();
    int off = wid ? ws[wid - 1] : 0;
    if (i < NE) rp[i] = off + inc - v;
    if (tid == 1023) g_part[g * 128 + blockIdx.x] = off + inc;
}
// phase B: exclusive scan of the 98 block sums; writes rowptr[NE] = total
__global__ void scanB(int nblk) {
    __shared__ int ws[4];
    int g = blockIdx.y, tid = threadIdx.x, lane = tid & 31, wid = tid >> 5;
    int v = (tid < nblk) ? g_part[g * 128 + tid] : 0;
    int inc = v;
#pragma unroll
    for (int o = 1; o < 32; o <<= 1) {
        int x = __shfl_up_sync(0xFFFFFFFFu, inc, o);
        if (lane >= o) inc += x;
    }
    if (lane == 31) ws[wid] = inc;
    __syncthreads();
    int woff = 0;
    for (int w = 0; w < wid; ++w) woff += ws[w];
    int excl = woff + inc - v;
    if (tid < nblk) g_part[g * 128 + tid] = excl;
    if (tid == nblk - 1) (g ? g_rpC : g_rpB)[NE] = excl + v;
}
// phase C: add block offsets, init cursors
__global__ void scanC() {
    int g = blockIdx.y;
    int i = blockIdx.x * 1024 + threadIdx.x;
    if (i >= NE) return;
    int* rp  = g ? g_rpC  : g_rpB;
    int* cur = g ? g_curC : g_curB;
    int val = rp[i] + g_part[g * 128 + blockIdx.x];
    rp[i] = val;
    cur[i] = val;
}
__global__ void scatter_both(const int* __restrict__ b_src, const int* __restrict__ b_dst,
                             const int* __restrict__ c_src, const int* __restrict__ c_dst,
                             const float* __restrict__ cf_ew, int E) {
    int i = blockIdx.x * blockDim.x + threadIdx.x;
    if (i >= E) return;
    if (blockIdx.y) {
        int pos = atomicAdd(&g_curC[c_dst[i]], 1);
        g_esrcC[pos] = c_src[i];
        g_ewC[pos] = cf_ew[i];
    } else {
        int pos = atomicAdd(&g_curB[b_dst[i]], 1);
        g_esrcB[pos] = b_src[i];
    }
}

// ---------------- mean aggregation on hi/lo planes: warp per destination ----------------
template <int WEIGHTED>
__global__ void aggregate_kernel(const bf16* __restrict__ sh, const bf16* __restrict__ sl,
                                 bf16* __restrict__ oh, bf16* __restrict__ ol,
                                 const int* __restrict__ rowptr, const int* __restrict__ esrc,
                                 const float* __restrict__ ew, int n) {
    int gw = (blockIdx.x * blockDim.x + threadIdx.x) >> 5;
    int lane = threadIdx.x & 31;
    if (gw >= n) return;
    int s0 = rowptr[gw], s1 = rowptr[gw + 1];
    float a0 = 0.f, a1 = 0.f, a2 = 0.f, a3 = 0.f;
    for (int j = s0; j < s1; ++j) {
        int sidx = esrc[j];
        uint2 uh = *(const uint2*)(sh + (size_t)sidx * D + lane * 4);
        uint2 ul = *(const uint2*)(sl + (size_t)sidx * D + lane * 4);
        float w = WEIGHTED ? ew[j] : 1.0f;
        a0 += (blo(uh.x) + blo(ul.x)) * w;
        a1 += (bhi(uh.x) + bhi(ul.x)) * w;
        a2 += (blo(uh.y) + blo(ul.y)) * w;
        a3 += (bhi(uh.y) + bhi(ul.y)) * w;
    }
    float inv = 1.0f / fmaxf((float)(s1 - s0), 1.0f);
    a0 *= inv; a1 *= inv; a2 *= inv; a3 *= inv;
    bf16 h0 = __float2bfloat16(a0), h1 = __float2bfloat16(a1);
    bf16 h2 = __float2bfloat16(a2), h3 = __float2bfloat16(a3);
    bf16 l0 = __float2bfloat16(a0 - __bfloat162float(h0));
    bf16 l1 = __float2bfloat16(a1 - __bfloat162float(h1));
    bf16 l2 = __float2bfloat16(a2 - __bfloat162float(h2));
    bf16 l3 = __float2bfloat16(a3 - __bfloat162float(h3));
    *(uint2*)(oh + (size_t)gw * D + lane * 4) = make_uint2(packbf(h0, h1), packbf(h2, h3));
    *(uint2*)(ol + (size_t)gw * D + lane * 4) = make_uint2(packbf(l0, l1), packbf(l2, l3));
}

// ---------------- launch ----------------
extern "C" void kernel_launch(void* const* d_in, const int* in_sizes, int n_in,
                              void* d_out, int out_size) {
    const float* ii      = (const float*)d_in[0];
    const float* e_emb   = (const float*)d_in[1];
    const float* k_emb   = (const float*)d_in[2];
    const float* cf_ew   = (const float*)d_in[3];
    const int*   b_src   = (const int*)d_in[4];
    const int*   b_dst   = (const int*)d_in[5];
    const int*   c_src   = (const int*)d_in[6];
    const int*   c_dst   = (const int*)d_in[7];
    const float* ek_self = (const float*)d_in[8];
    const float* ek_neigh= (const float*)d_in[9];
    const float* ek_bias = (const float*)d_in[10];
    const float* ee_self = (const float*)d_in[11];
    const float* ee_neigh= (const float*)d_in[12];
    const float* ee_bias = (const float*)d_in[13];
    const float* w1W = (const float*)d_in[14];
    const float* w1b = (const float*)d_in[15];
    const float* w2W = (const float*)d_in[16];
    const float* w2b = (const float*)d_in[17];
    const float* w3W = (const float*)d_in[18];
    const float* w3b = (const float*)d_in[19];
    const float* w4W = (const float*)d_in[20];
    const float* w4b = (const float*)d_in[21];
    const float* combW = (const float*)d_in[22];
    const float* combb = (const float*)d_in[23];
    float* out = (float*)d_out;

    int n_k = in_sizes[0] / D;
    int n_e = in_sizes[1] / D;
    int E   = in_sizes[4];

    bf16 *eeh, *eel, *iih, *iil, *keh, *kel, *ii2h, *ii2l;
    bf16 *nbh, *nbl, *nch, *ncl, *tmph, *tmpl, *hiIh, *hiIl, *hiSh, *hiSl, *sch, *scl;
    bf16 *Wh, *Wl;
    float *p_c1, *p_c2, *p_ewC;
    int *p_rpB, *p_rpC, *p_esB, *p_esC;
    cudaGetSymbolAddress((void**)&eeh, g_eeh);   cudaGetSymbolAddress((void**)&eel, g_eel);
    cudaGetSymbolAddress((void**)&iih, g_iih);   cudaGetSymbolAddress((void**)&iil, g_iil);
    cudaGetSymbolAddress((void**)&keh, g_keh);   cudaGetSymbolAddress((void**)&kel, g_kel);
    cudaGetSymbolAddress((void**)&ii2h, g_ii2h); cudaGetSymbolAddress((void**)&ii2l, g_ii2l);
    cudaGetSymbolAddress((void**)&nbh, g_nbh);   cudaGetSymbolAddress((void**)&nbl, g_nbl);
    cudaGetSymbolAddress((void**)&nch, g_nch);   cudaGetSymbolAddress((void**)&ncl, g_ncl);
    cudaGetSymbolAddress((void**)&tmph, g_tmph); cudaGetSymbolAddress((void**)&tmpl, g_tmpl);
    cudaGetSymbolAddress((void**)&hiIh, g_hiIh); cudaGetSymbolAddress((void**)&hiIl, g_hiIl);
    cudaGetSymbolAddress((void**)&hiSh, g_hiSh); cudaGetSymbolAddress((void**)&hiSl, g_hiSl);
    cudaGetSymbolAddress((void**)&sch, g_sch);   cudaGetSymbolAddress((void**)&scl, g_scl);
    cudaGetSymbolAddress((void**)&Wh, g_Wh);     cudaGetSymbolAddress((void**)&Wl, g_Wl);
    cudaGetSymbolAddress((void**)&p_c1, g_c1);   cudaGetSymbolAddress((void**)&p_c2, g_c2);
    cudaGetSymbolAddress((void**)&p_rpB, g_rpB); cudaGetSymbolAddress((void**)&p_rpC, g_rpC);
    cudaGetSymbolAddress((void**)&p_esB, g_esrcB); cudaGetSymbolAddress((void**)&p_esC, g_esrcC);
    cudaGetSymbolAddress((void**)&p_ewC, g_ewC);

    cudaFuncSetAttribute(gemm_mma<0, 0>, cudaFuncAttributeMaxDynamicSharedMemorySize, SM_TOTAL);
    cudaFuncSetAttribute(gemm_mma<1, 0>, cudaFuncAttributeMaxDynamicSharedMemorySize, SM_TOTAL);
    cudaFuncSetAttribute(gemm_mma<2, 1>, cudaFuncAttributeMaxDynamicSharedMemorySize, SM_TOTAL);

    int gE   = (E + 255) / 256;
    int gNe  = (n_e + 255) / 256;
    int gSc  = (n_e + 1023) / 1024;              // 98
    int gAgg = (n_e * 32 + 255) / 256;
    int gbK  = (n_k + 127) / 128;
    int gbE  = (n_e + 127) / 128;

    // 0, 1: fused prep
    prep1<<<60257, 256>>>(e_emb, ii, k_emb, w2W, w2b, w3W, w3b,
                          ek_self + DD, ek_neigh + DD, ee_self + DD, ee_neigh + DD,
                          ek_bias + D, ee_bias + D);
    prep2<<<7 * 128, 256>>>(w4W, ek_self, ek_neigh, w1W, ee_self, ee_neigh, combW);
    // 2-4: CSR start (both graphs)
    zero_both<<<dim3(gNe, 2), 256>>>();
    count_both<<<dim3(gE, 2), 256>>>(b_dst, c_dst, E);
    scanA<<<dim3(gSc, 2), 1024>>>();
    // 5: ii2 = [ii ; k_emb] @ w4^T + w4_b   (ncu -s 5 -c 1 captures this launch)
    gemm_mma<0, 0><<<gbK, 256, SM_TOTAL>>>(iih, iil, keh, kel,
                                           Wh + 0*32768, Wl + 0*32768, w4b,
                                           ii2h, ii2l, nullptr, n_k);
    // 6-8: finish CSR
    scanB<<<dim3(1, 2), 128>>>(gSc);
    scanC<<<dim3(gSc, 2), 1024>>>();
    scatter_both<<<dim3(gE, 2), 256>>>(b_src, b_dst, c_src, c_dst, cf_ew, E);
    // 9: belong mean aggregation of ii2 (shared by both layers)
    aggregate_kernel<0><<<gAgg, 256>>>(ii2h, ii2l, nbh, nbl, p_rpB, p_esB, nullptr, n_e);
    // 10-11: belong layer0 (relu) then folded layer1+w2
    gemm_mma<1, 0><<<gbE, 256, SM_TOTAL>>>(eeh, eel, nbh, nbl,
                                           Wh + 1*32768, Wl + 1*32768, ek_bias,
                                           tmph, tmpl, nullptr, n_e);
    gemm_mma<0, 0><<<gbE, 256, SM_TOTAL>>>(tmph, tmpl, nbh, nbl,
                                           Wh + 2*32768, Wl + 2*32768, p_c1,
                                           hiIh, hiIl, nullptr, n_e);
    // 12: src_com = [h_iI ; e_emb] @ w1^T + w1_b
    gemm_mma<0, 0><<<gbE, 256, SM_TOTAL>>>(hiIh, hiIl, eeh, eel,
                                           Wh + 3*32768, Wl + 3*32768, w1b,
                                           sch, scl, nullptr, n_e);
    // 13: collab weighted mean aggregation of src_com
    aggregate_kernel<1><<<gAgg, 256>>>(sch, scl, nch, ncl, p_rpC, p_esC, p_ewC, n_e);
    // 14-15: collab layer0 (relu) then folded layer1+w3
    gemm_mma<1, 0><<<gbE, 256, SM_TOTAL>>>(eeh, eel, nch, ncl,
                                           Wh + 4*32768, Wl + 4*32768, ee_bias,
                                           tmph, tmpl, nullptr, n_e);
    gemm_mma<0, 0><<<gbE, 256, SM_TOTAL>>>(tmph, tmpl, nch, ncl,
                                           Wh + 5*32768, Wl + 5*32768, p_c2,
                                           hiSh, hiSl, nullptr, n_e);
    // 16: final leaky_relu([h_iI ; h_iS] @ comb^T + comb_b) -> fp32 out
    gemm_mma<2, 1><<<gbE, 256, SM_TOTAL>>>(hiIh, hiIl, hiSh, hiSl,
                                           Wh + 6*32768, Wl + 6*32768, combb,
                                           nullptr, nullptr, out, n_e);
}

// round 6
// speedup vs baseline: 3.4647x; 1.9789x over previous
#include <cuda_runtime.h>
#include <cuda_fp16.h>
#include <cstdint>

typedef __half h16;
#define NK   10000
#define NE   100000
#define D    128
#define DD   (128*128)
#define EDG  1600000

// ---------------- scratch (static __device__ — no allocations allowed) ----------------
__device__ __align__(16) h16 g_ee[NE*D];
__device__ __align__(16) h16 g_ii[NK*D];
__device__ __align__(16) h16 g_ke[NK*D];
__device__ __align__(16) h16 g_ii2[NK*D];
__device__ __align__(16) h16 g_nb[NE*D];
__device__ __align__(16) h16 g_nc[NE*D];
__device__ __align__(16) h16 g_tmp[NE*D];
__device__ __align__(16) h16 g_hiI[NE*D];
__device__ __align__(16) h16 g_hiS[NE*D];
__device__ __align__(16) h16 g_sc[NE*D];
__device__ __align__(16) h16 g_W[7][128*256];       // per stage [128 n][256 k]
__device__ __align__(16) float g_M1[DD], g_M2[DD], g_M3[DD], g_M4[DD];
__device__ __align__(16) float g_c1[D], g_c2[D];
// CSR (B = belong, C = collab)
__device__ __align__(16) int   g_degB[NE], g_degC[NE];
__device__ __align__(16) int   g_rpB[NE+1], g_rpC[NE+1];
__device__ __align__(16) int   g_curB[NE], g_curC[NE];
__device__ __align__(16) int   g_esrcB[EDG], g_esrcC[EDG];
__device__ __align__(16) float g_ewC[EDG];
__device__ __align__(16) int   g_part[2*128];

// ---------------- small helpers ----------------
__device__ __forceinline__ uint32_t s2u(const void* p) {
    uint32_t a;
    asm("{ .reg .u64 t; cvta.to.shared.u64 t, %1; cvt.u32.u64 %0, t; }" : "=r"(a) : "l"(p));
    return a;
}
__device__ __forceinline__ uint32_t packh(h16 a, h16 b) {
    return ((uint32_t)__half_as_ushort(b) << 16) | (uint32_t)__half_as_ushort(a);
}
__device__ __forceinline__ float hlo(uint32_t u) {
    return __half2float(__ushort_as_half((unsigned short)(u & 0xFFFF)));
}
__device__ __forceinline__ float hhi(uint32_t u) {
    return __half2float(__ushort_as_half((unsigned short)(u >> 16)));
}
__device__ __forceinline__ void ldmx4(uint32_t* r, uint32_t addr) {
    asm volatile("ldmatrix.sync.aligned.m8n8.x4.shared.b16 {%0,%1,%2,%3}, [%4];"
                 : "=r"(r[0]), "=r"(r[1]), "=r"(r[2]), "=r"(r[3]) : "r"(addr));
}
__device__ __forceinline__ void mma16816(float* c, const uint32_t* a, uint32_t b0, uint32_t b1) {
    asm volatile("mma.sync.aligned.m16n8k16.row.col.f32.f16.f16.f32 "
                 "{%0,%1,%2,%3}, {%4,%5,%6,%7}, {%8,%9}, {%0,%1,%2,%3};"
                 : "+f"(c[0]), "+f"(c[1]), "+f"(c[2]), "+f"(c[3])
                 : "r"(a[0]), "r"(a[1]), "r"(a[2]), "r"(a[3]), "r"(b0), "r"(b1));
}
__device__ __forceinline__ void cp16(uint32_t s, const void* g) {
    asm volatile("cp.async.cg.shared.global [%0], [%1], 16;" :: "r"(s), "l"(g));
}

// ---------------- SMEM layout (padded 144B rows, linear addressing) ----------------
// buffer b (0/1): A chunk at b*36864, B chunk at b*36864 + 18432. Each 128 rows x 144B.
#define T_ROW    144
#define CH_B     18432
#define CH_BUF   36864
#define SM_TOTAL 73728             // 2 buffers; epilogue C tile reuses region [0, ...)
#define CF_ROW   528               // fp32 epilogue row stride (67584 <= 73728)
#define CH_ROW   272               // fp16 epilogue row stride (34816)

// ---------------- single-pass fp16 GEMM on mma.sync (HMMA) ----------------
// C[M,128] = act( A1[M,128]@W[:,0:128]^T + A2[M,128]@W[:,128:256]^T + bias )
template <int ACT, int OUTF32>
__global__ void __launch_bounds__(256, 2) gemm_h(
    const h16* __restrict__ a1, const h16* __restrict__ a2,
    const h16* __restrict__ w,  const float* __restrict__ bias,
    h16* __restrict__ oh, float* __restrict__ of, int M)
{
    extern __shared__ char smem[];
    uint32_t sb = s2u(smem);
    int tid = threadIdx.x, lane = tid & 31, wid = tid >> 5;
    int wr = wid & 3, wc = wid >> 2;            // warp grid 4 (m) x 2 (n)
    int mbrow = blockIdx.x * 128;

    auto load_chunk = [&](int c, int buf) {
        const h16* A = (c < 2) ? a1 : a2;
        int k0 = (c & 1) * 64;
#pragma unroll
        for (int u = 0; u < 4; ++u) {           // A: 1024 16B granules
            int i = u * 256 + tid;
            int row = i >> 3, g = i & 7;
            int grow = mbrow + row;
            if (grow < M)
                cp16(sb + buf * CH_BUF + row * T_ROW + g * 16,
                     A + (size_t)grow * 128 + k0 + g * 8);
        }
#pragma unroll
        for (int u = 0; u < 4; ++u) {           // B: 1024 granules
            int i = u * 256 + tid;
            int n = i >> 3, g = i & 7;
            cp16(sb + buf * CH_BUF + CH_B + n * T_ROW + g * 16,
                 w + n * 256 + c * 64 + g * 8);
        }
        asm volatile("cp.async.commit_group;" ::: "memory");
    };

    load_chunk(0, 0);
    load_chunk(1, 1);

    float acc[2][8][4];
#pragma unroll
    for (int mi = 0; mi < 2; ++mi)
#pragma unroll
        for (int ni = 0; ni < 8; ++ni)
#pragma unroll
            for (int q = 0; q < 4; ++q) acc[mi][ni][q] = 0.f;

    int l15 = lane & 15, lkb = (lane >> 4) * 16;

    for (int c = 0; c < 4; ++c) {
        if (c < 3) asm volatile("cp.async.wait_group 1;" ::: "memory");
        else       asm volatile("cp.async.wait_group 0;" ::: "memory");
        __syncthreads();

        int buf = c & 1;
        uint32_t Ab = sb + buf * CH_BUF + (uint32_t)(wr * 32 + l15) * T_ROW + lkb;
        uint32_t Bb = sb + buf * CH_BUF + CH_B + (uint32_t)(wc * 64 + l15) * T_ROW + lkb;
#pragma unroll
        for (int s = 0; s < 4; ++s) {
            uint32_t Aks = Ab + s * 32;
            uint32_t Bks = Bb + s * 32;
            uint32_t A0[4], A1[4];
            ldmx4(A0, Aks);
            ldmx4(A1, Aks + 16 * T_ROW);
            uint32_t B[4][4];
#pragma unroll
            for (int nb = 0; nb < 4; ++nb) ldmx4(B[nb], Bks + nb * (16 * T_ROW));
#pragma unroll
            for (int ni = 0; ni < 8; ++ni) {
                int nb = ni >> 1, hb = ni & 1;
                mma16816(acc[0][ni], A0, B[nb][hb], B[nb][2 + hb]);
                mma16816(acc[1][ni], A1, B[nb][hb], B[nb][2 + hb]);
            }
        }
        __syncthreads();
        if (c + 2 < 4) load_chunk(c + 2, buf);
    }

    // ---- epilogue: acc -> smem tile (bias+act applied) -> coalesced stores ----
    int quad = lane >> 2, tq = lane & 3;
#pragma unroll
    for (int ni = 0; ni < 8; ++ni) {
        int cbase = wc * 64 + ni * 8 + tq * 2;
        float bv0 = __ldg(bias + cbase), bv1 = __ldg(bias + cbase + 1);
#pragma unroll
        for (int mi = 0; mi < 2; ++mi) {
#pragma unroll
            for (int h = 0; h < 2; ++h) {
                int row = wr * 32 + mi * 16 + quad + h * 8;
                float x0 = acc[mi][ni][2 * h + 0] + bv0;
                float x1 = acc[mi][ni][2 * h + 1] + bv1;
                if (ACT == 1) { x0 = fmaxf(x0, 0.f); x1 = fmaxf(x1, 0.f); }
                if (ACT == 2) { x0 = (x0 >= 0.f) ? x0 : 0.2f * x0;
                                x1 = (x1 >= 0.f) ? x1 : 0.2f * x1; }
                if (OUTF32)
                    *(float2*)(smem + row * CF_ROW + cbase * 4) = make_float2(x0, x1);
                else
                    *(uint32_t*)(smem + row * CH_ROW + cbase * 2) =
                        packh(__float2half_rn(x0), __float2half_rn(x1));
            }
        }
    }
    __syncthreads();

    if (OUTF32) {
#pragma unroll
        for (int it = 0; it < 16; ++it) {       // 1 row per warp per iter, 512B row
            int r = wid * 16 + it;
            int grow = mbrow + r;
            if (grow >= M) continue;
            float4 v = *(float4*)(smem + r * CF_ROW + lane * 16);
            *(float4*)(of + (size_t)grow * 128 + lane * 4) = v;
        }
    } else {
        int row2 = lane >> 4, colg = lane & 15; // 2 rows per warp per iter, 256B row
#pragma unroll
        for (int it = 0; it < 8; ++it) {
            int r = wid * 16 + it * 2 + row2;
            int grow = mbrow + r;
            if (grow >= M) continue;
            uint4 v = *(uint4*)(smem + r * CH_ROW + colg * 16);
            *(uint4*)(oh + (size_t)grow * 128 + colg * 8) = v;
        }
    }
}

// ---------------- prep1: fp16 convert (ee/ii/ke) + fold_mats + fold_bias ----------------
__global__ void prep1(const float* __restrict__ e_emb, const float* __restrict__ ii,
                      const float* __restrict__ k_emb,
                      const float* __restrict__ w2W, const float* __restrict__ w2b,
                      const float* __restrict__ w3W, const float* __restrict__ w3b,
                      const float* __restrict__ ekS1, const float* __restrict__ ekN1,
                      const float* __restrict__ eeS1, const float* __restrict__ eeN1,
                      const float* __restrict__ ekb1, const float* __restrict__ eeb1) {
    int bid = blockIdx.x, tid = threadIdx.x;
    if (bid < 50000) {
        int i = bid * 256 + tid;
        g_ee[i] = __float2half_rn(e_emb[i]);
    } else if (bid < 55000) {
        int i = (bid - 50000) * 256 + tid;
        g_ii[i] = __float2half_rn(ii[i]);
    } else if (bid < 60000) {
        int i = (bid - 55000) * 256 + tid;
        g_ke[i] = __float2half_rn(k_emb[i]);
    } else if (bid < 60256) {                   // fold_mats: M = A @ B
        int lb = bid - 60000;
        int mat = lb >> 6;
        int idx = (lb & 63) * 256 + tid;
        const float* A = (mat < 2) ? w2W : w3W;
        const float* B = (mat == 0) ? ekS1 : (mat == 1) ? ekN1 : (mat == 2) ? eeS1 : eeN1;
        float* O = (mat == 0) ? g_M1 : (mat == 1) ? g_M2 : (mat == 2) ? g_M3 : g_M4;
        int n = idx >> 7, k = idx & 127;
        float acc = 0.f;
#pragma unroll 8
        for (int j = 0; j < 128; ++j)
            acc += A[n * 128 + j] * B[j * 128 + k];
        O[idx] = acc;
    } else {
        int t = tid;
        if (t < 128) {
            float a = 0.f, b = 0.f;
#pragma unroll 8
            for (int j = 0; j < 128; ++j) {
                a += w2W[t * 128 + j] * ekb1[j];
                b += w3W[t * 128 + j] * eeb1[j];
            }
            g_c1[t] = a + w2b[t];
            g_c2[t] = b + w3b[t];
        }
    }
}

// ---------------- prep2: fp16 convert all 7 stage weight matrices ----------------
__global__ void prep2(const float* __restrict__ w4W, const float* __restrict__ ek_self,
                      const float* __restrict__ ek_neigh, const float* __restrict__ w1W,
                      const float* __restrict__ ee_self, const float* __restrict__ ee_neigh,
                      const float* __restrict__ combW) {
    int bid = blockIdx.x;
    int stage = bid >> 7;
    int idx = (bid & 127) * 256 + threadIdx.x;
    const float* a; const float* b;
    switch (stage) {
        case 0: a = w4W;     b = nullptr;   break;
        case 1: a = ek_self; b = ek_neigh;  break;
        case 2: a = g_M1;    b = g_M2;      break;
        case 3: a = w1W;     b = nullptr;   break;
        case 4: a = ee_self; b = ee_neigh;  break;
        case 5: a = g_M3;    b = g_M4;      break;
        default: a = combW;  b = nullptr;   break;
    }
    int n = idx >> 8, k = idx & 255;
    float v = b ? (k < 128 ? a[n * 128 + k] : b[n * 128 + (k - 128)]) : a[idx];
    g_W[stage][idx] = __float2half_rn(v);
}

// ---------------- CSR build (both graphs via gridDim.y) ----------------
__global__ void zero_both() {
    int i = blockIdx.x * blockDim.x + threadIdx.x;
    if (i < NE) (blockIdx.y ? g_degC : g_degB)[i] = 0;
}
__global__ void count_both(const int* __restrict__ b_dst, const int* __restrict__ c_dst, int E) {
    int i = blockIdx.x * blockDim.x + threadIdx.x;
    if (i >= E) return;
    if (blockIdx.y) atomicAdd(&g_degC[c_dst[i]], 1);
    else            atomicAdd(&g_degB[b_dst[i]], 1);
}
__global__ void scanA() {
    __shared__ int ws[32];
    int g = blockIdx.y, tid = threadIdx.x, lane = tid & 31, wid = tid >> 5;
    int* deg = g ? g_degC : g_degB;
    int* rp  = g ? g_rpC  : g_rpB;
    int i = blockIdx.x * 1024 + tid;
    int v = (i < NE) ? deg[i] : 0;
    int inc = v;
#pragma unroll
    for (int o = 1; o < 32; o <<= 1) {
        int x = __shfl_up_sync(0xFFFFFFFFu, inc, o);
        if (lane >= o) inc += x;
    }
    if (lane == 31) ws[wid] = inc;
    __syncthreads();
    if (wid == 0) {
        int s = ws[lane];
#pragma unroll
        for (int o = 1; o < 32; o <<= 1) {
            int x = __shfl_up_sync(0xFFFFFFFFu, s, o);
            if (lane >= o) s += x;
        }
        ws[lane] = s;
    }
    __syncthreads();
    int off = wid ? ws[wid - 1] : 0;
    if (i < NE) rp[i] = off + inc - v;
    if (tid == 1023) g_part[g * 128 + blockIdx.x] = off + inc;
}
__global__ void scanB(int nblk) {
    __shared__ int ws[4];
    int g = blockIdx.y, tid = threadIdx.x, lane = tid & 31, wid = tid >> 5;
    int v = (tid < nblk) ? g_part[g * 128 + tid] : 0;
    int inc = v;
#pragma unroll
    for (int o = 1; o < 32; o <<= 1) {
        int x = __shfl_up_sync(0xFFFFFFFFu, inc, o);
        if (lane >= o) inc += x;
    }
    if (lane == 31) ws[wid] = inc;
    __syncthreads();
    int woff = 0;
    for (int w = 0; w < wid; ++w) woff += ws[w];
    int excl = woff + inc - v;
    if (tid < nblk) g_part[g * 128 + tid] = excl;
    if (tid == nblk - 1) (g ? g_rpC : g_rpB)[NE] = excl + v;
}
__global__ void scanC() {
    int g = blockIdx.y;
    int i = blockIdx.x * 1024 + threadIdx.x;
    if (i >= NE) return;
    int* rp  = g ? g_rpC  : g_rpB;
    int* cur = g ? g_curC : g_curB;
    int val = rp[i] + g_part[g * 128 + blockIdx.x];
    rp[i] = val;
    cur[i] = val;
}
__global__ void scatter_both(const int* __restrict__ b_src, const int* __restrict__ b_dst,
                             const int* __restrict__ c_src, const int* __restrict__ c_dst,
                             const float* __restrict__ cf_ew, int E) {
    int i = blockIdx.x * blockDim.x + threadIdx.x;
    if (i >= E) return;
    if (blockIdx.y) {
        int pos = atomicAdd(&g_curC[c_dst[i]], 1);
        g_esrcC[pos] = c_src[i];
        g_ewC[pos] = cf_ew[i];
    } else {
        int pos = atomicAdd(&g_curB[b_dst[i]], 1);
        g_esrcB[pos] = b_src[i];
    }
}

// ---------------- mean aggregation (fp16 plane, fp32 accum): warp per destination ----------------
template <int WEIGHTED>
__global__ void aggregate_kernel(const h16* __restrict__ sh, h16* __restrict__ oh,
                                 const int* __restrict__ rowptr, const int* __restrict__ esrc,
                                 const float* __restrict__ ew, int n) {
    int gw = (blockIdx.x * blockDim.x + threadIdx.x) >> 5;
    int lane = threadIdx.x & 31;
    if (gw >= n) return;
    int s0 = rowptr[gw], s1 = rowptr[gw + 1];
    float a0 = 0.f, a1 = 0.f, a2 = 0.f, a3 = 0.f;
    for (int j = s0; j < s1; ++j) {
        int sidx = esrc[j];
        uint2 u = *(const uint2*)(sh + (size_t)sidx * D + lane * 4);
        float w = WEIGHTED ? ew[j] : 1.0f;
        a0 += hlo(u.x) * w;
        a1 += hhi(u.x) * w;
        a2 += hlo(u.y) * w;
        a3 += hhi(u.y) * w;
    }
    float inv = 1.0f / fmaxf((float)(s1 - s0), 1.0f);
    a0 *= inv; a1 *= inv; a2 *= inv; a3 *= inv;
    *(uint2*)(oh + (size_t)gw * D + lane * 4) =
        make_uint2(packh(__float2half_rn(a0), __float2half_rn(a1)),
                   packh(__float2half_rn(a2), __float2half_rn(a3)));
}

// ---------------- launch ----------------
extern "C" void kernel_launch(void* const* d_in, const int* in_sizes, int n_in,
                              void* d_out, int out_size) {
    const float* ii      = (const float*)d_in[0];
    const float* e_emb   = (const float*)d_in[1];
    const float* k_emb   = (const float*)d_in[2];
    const float* cf_ew   = (const float*)d_in[3];
    const int*   b_src   = (const int*)d_in[4];
    const int*   b_dst   = (const int*)d_in[5];
    const int*   c_src   = (const int*)d_in[6];
    const int*   c_dst   = (const int*)d_in[7];
    const float* ek_self = (const float*)d_in[8];
    const float* ek_neigh= (const float*)d_in[9];
    const float* ek_bias = (const float*)d_in[10];
    const float* ee_self = (const float*)d_in[11];
    const float* ee_neigh= (const float*)d_in[12];
    const float* ee_bias = (const float*)d_in[13];
    const float* w1W = (const float*)d_in[14];
    const float* w1b = (const float*)d_in[15];
    const float* w2W = (const float*)d_in[16];
    const float* w2b = (const float*)d_in[17];
    const float* w3W = (const float*)d_in[18];
    const float* w3b = (const float*)d_in[19];
    const float* w4W = (const float*)d_in[20];
    const float* w4b = (const float*)d_in[21];
    const float* combW = (const float*)d_in[22];
    const float* combb = (const float*)d_in[23];
    float* out = (float*)d_out;

    int n_k = in_sizes[0] / D;
    int n_e = in_sizes[1] / D;
    int E   = in_sizes[4];

    h16 *ee, *iip, *ke, *ii2, *nb, *nc, *tmp, *hiI, *hiS, *sc, *W;
    float *p_c1, *p_c2, *p_ewC;
    int *p_rpB, *p_rpC, *p_esB, *p_esC;
    cudaGetSymbolAddress((void**)&ee,  g_ee);
    cudaGetSymbolAddress((void**)&iip, g_ii);
    cudaGetSymbolAddress((void**)&ke,  g_ke);
    cudaGetSymbolAddress((void**)&ii2, g_ii2);
    cudaGetSymbolAddress((void**)&nb,  g_nb);
    cudaGetSymbolAddress((void**)&nc,  g_nc);
    cudaGetSymbolAddress((void**)&tmp, g_tmp);
    cudaGetSymbolAddress((void**)&hiI, g_hiI);
    cudaGetSymbolAddress((void**)&hiS, g_hiS);
    cudaGetSymbolAddress((void**)&sc,  g_sc);
    cudaGetSymbolAddress((void**)&W,   g_W);
    cudaGetSymbolAddress((void**)&p_c1, g_c1);   cudaGetSymbolAddress((void**)&p_c2, g_c2);
    cudaGetSymbolAddress((void**)&p_rpB, g_rpB); cudaGetSymbolAddress((void**)&p_rpC, g_rpC);
    cudaGetSymbolAddress((void**)&p_esB, g_esrcB); cudaGetSymbolAddress((void**)&p_esC, g_esrcC);
    cudaGetSymbolAddress((void**)&p_ewC, g_ewC);

    cudaFuncSetAttribute(gemm_h<0, 0>, cudaFuncAttributeMaxDynamicSharedMemorySize, SM_TOTAL);
    cudaFuncSetAttribute(gemm_h<1, 0>, cudaFuncAttributeMaxDynamicSharedMemorySize, SM_TOTAL);
    cudaFuncSetAttribute(gemm_h<2, 1>, cudaFuncAttributeMaxDynamicSharedMemorySize, SM_TOTAL);

    int gE   = (E + 255) / 256;
    int gNe  = (n_e + 255) / 256;
    int gSc  = (n_e + 1023) / 1024;
    int gAgg = (n_e * 32 + 255) / 256;
    int gbK  = (n_k + 127) / 128;
    int gbE  = (n_e + 127) / 128;

    // prep
    prep1<<<60257, 256>>>(e_emb, ii, k_emb, w2W, w2b, w3W, w3b,
                          ek_self + DD, ek_neigh + DD, ee_self + DD, ee_neigh + DD,
                          ek_bias + D, ee_bias + D);
    prep2<<<7 * 128, 256>>>(w4W, ek_self, ek_neigh, w1W, ee_self, ee_neigh, combW);
    // CSR (both graphs)
    zero_both<<<dim3(gNe, 2), 256>>>();
    count_both<<<dim3(gE, 2), 256>>>(b_dst, c_dst, E);
    scanA<<<dim3(gSc, 2), 1024>>>();
    // ii2 = [ii ; k_emb] @ w4^T + w4_b
    gemm_h<0, 0><<<gbK, 256, SM_TOTAL>>>(iip, ke, W + 0*32768, w4b, ii2, nullptr, n_k);
    scanB<<<dim3(1, 2), 128>>>(gSc);
    scanC<<<dim3(gSc, 2), 1024>>>();
    scatter_both<<<dim3(gE, 2), 256>>>(b_src, b_dst, c_src, c_dst, cf_ew, E);
    // belong mean aggregation (shared by both layers)
    aggregate_kernel<0><<<gAgg, 256>>>(ii2, nb, p_rpB, p_esB, nullptr, n_e);
    // belong layer0 (relu) then folded layer1+w2
    gemm_h<1, 0><<<gbE, 256, SM_TOTAL>>>(ee, nb, W + 1*32768, ek_bias, tmp, nullptr, n_e);
    gemm_h<0, 0><<<gbE, 256, SM_TOTAL>>>(tmp, nb, W + 2*32768, p_c1, hiI, nullptr, n_e);
    // src_com = [h_iI ; e_emb] @ w1^T + w1_b
    gemm_h<0, 0><<<gbE, 256, SM_TOTAL>>>(hiI, ee, W + 3*32768, w1b, sc, nullptr, n_e);
    // collab weighted mean aggregation
    aggregate_kernel<1><<<gAgg, 256>>>(sc, nc, p_rpC, p_esC, p_ewC, n_e);
    // collab layer0 (relu) then folded layer1+w3
    gemm_h<1, 0><<<gbE, 256, SM_TOTAL>>>(ee, nc, W + 4*32768, ee_bias, tmp, nullptr, n_e);
    gemm_h<0, 0><<<gbE, 256, SM_TOTAL>>>(tmp, nc, W + 5*32768, p_c2, hiS, nullptr, n_e);
    // final leaky_relu([h_iI ; h_iS] @ comb^T + comb_b) -> fp32 out
    gemm_h<2, 1><<<gbE, 256, SM_TOTAL>>>(hiI, hiS, W + 6*32768, combb, nullptr, out, n_e);
}

// round 7
// speedup vs baseline: 3.5974x; 1.0383x over previous
#include <cuda_runtime.h>
#include <cuda_fp16.h>
#include <cstdint>

typedef __half h16;
#define NK   10000
#define NE   100000
#define D    128
#define DD   (128*128)
#define EDG  1600000

// ---------------- scratch (static __device__ — no allocations allowed) ----------------
__device__ __align__(16) h16 g_ee[NE*D];
__device__ __align__(16) h16 g_ii[NK*D];
__device__ __align__(16) h16 g_ke[NK*D];
__device__ __align__(16) h16 g_ii2[NK*D];
__device__ __align__(16) h16 g_nb[NE*D];
__device__ __align__(16) h16 g_nc[NE*D];
__device__ __align__(16) h16 g_hiI[NE*D];
__device__ __align__(16) h16 g_sc[NE*D];
__device__ __align__(16) h16 g_W[7][128*256];       // per stage [128 n][256 k]
__device__ __align__(16) float g_M1[DD], g_M2[DD], g_M3[DD], g_M4[DD];
__device__ __align__(16) float g_c1[D], g_c2[D];
// CSR (B = belong, C = collab)
__device__ __align__(16) int   g_degB[NE], g_degC[NE];
__device__ __align__(16) int   g_rpB[NE+1], g_rpC[NE+1];
__device__ __align__(16) int   g_curB[NE], g_curC[NE];
__device__ __align__(16) int   g_esrcB[EDG], g_esrcC[EDG];
__device__ __align__(16) float g_ewC[EDG];
__device__ __align__(16) int   g_part[2*128];

// ---------------- small helpers ----------------
__device__ __forceinline__ uint32_t s2u(const void* p) {
    uint32_t a;
    asm("{ .reg .u64 t; cvta.to.shared.u64 t, %1; cvt.u32.u64 %0, t; }" : "=r"(a) : "l"(p));
    return a;
}
__device__ __forceinline__ uint32_t packh(h16 a, h16 b) {
    return ((uint32_t)__half_as_ushort(b) << 16) | (uint32_t)__half_as_ushort(a);
}
__device__ __forceinline__ float hlo(uint32_t u) {
    return __half2float(__ushort_as_half((unsigned short)(u & 0xFFFF)));
}
__device__ __forceinline__ float hhi(uint32_t u) {
    return __half2float(__ushort_as_half((unsigned short)(u >> 16)));
}
__device__ __forceinline__ void ldmx4(uint32_t* r, uint32_t addr) {
    asm volatile("ldmatrix.sync.aligned.m8n8.x4.shared.b16 {%0,%1,%2,%3}, [%4];"
                 : "=r"(r[0]), "=r"(r[1]), "=r"(r[2]), "=r"(r[3]) : "r"(addr));
}
__device__ __forceinline__ void mma16816(float* c, const uint32_t* a, uint32_t b0, uint32_t b1) {
    asm volatile("mma.sync.aligned.m16n8k16.row.col.f32.f16.f16.f32 "
                 "{%0,%1,%2,%3}, {%4,%5,%6,%7}, {%8,%9}, {%0,%1,%2,%3};"
                 : "+f"(c[0]), "+f"(c[1]), "+f"(c[2]), "+f"(c[3])
                 : "r"(a[0]), "r"(a[1]), "r"(a[2]), "r"(a[3]), "r"(b0), "r"(b1));
}
__device__ __forceinline__ void cp16(uint32_t s, const void* g) {
    asm volatile("cp.async.cg.shared.global [%0], [%1], 16;" :: "r"(s), "l"(g));
}

// ---------------- SMEM layout ----------------
// chunk double buffers [0, 73728): buf b: A at b*36864, B at b*36864+18432, rows 144B
// fp16 tile [73728, 108544): 128 rows x 272B (full 128-col fp16 row + pad)
// fp32 epilogue staging reuses [0, 67584) with 528B rows
#define T_ROW    144
#define CH_B     18432
#define CH_BUF   36864
#define TILE_OFF 73728
#define TT_ROW   272
#define SM_TOTAL 108544
#define CF_ROW   528

// ---------------- generic GEMM pass ----------------
// C[128,128] = act( Op1[128,128] @ W[:,0:128]^T + Op2[128,128] @ W[:,128:256]^T + bias )
// Op1 = chunks 0,1 (A1S: from smem tile, else gA1); Op2 = chunks 2,3 (A2S / gA2).
// OUT: 0 = smem tile only; 1 = smem tile + global fp16; 2 = global fp32.
template <int A1S, int A2S, int ACT, int OUT>
__device__ __forceinline__ void gpass(
    char* smem, uint32_t sb, int tid, int lane, int wid, int mbrow, int M,
    const h16* gA1, const h16* gA2, const h16* w, const float* bias,
    h16* go16, float* go32)
{
    int wr = wid & 3, wc = wid >> 2;            // warp grid 4 (m) x 2 (n)

    auto load_chunk = [&](int c, int buf) {
        int k0 = (c & 1) * 64;
        bool a_smem = (c < 2) ? (A1S != 0) : (A2S != 0);
        const h16* A = (c < 2) ? gA1 : gA2;
        if (!a_smem) {
#pragma unroll
            for (int u = 0; u < 4; ++u) {
                int i = u * 256 + tid;
                int row = i >> 3, g = i & 7;
                int grow = mbrow + row;
                if (grow < M)
                    cp16(sb + buf * CH_BUF + row * T_ROW + g * 16,
                         A + (size_t)grow * 128 + k0 + g * 8);
            }
        }
#pragma unroll
        for (int u = 0; u < 4; ++u) {
            int i = u * 256 + tid;
            int n = i >> 3, g = i & 7;
            cp16(sb + buf * CH_BUF + CH_B + n * T_ROW + g * 16,
                 w + n * 256 + c * 64 + g * 8);
        }
        asm volatile("cp.async.commit_group;" ::: "memory");
    };

    load_chunk(0, 0);
    load_chunk(1, 1);

    float acc[2][8][4];
#pragma unroll
    for (int mi = 0; mi < 2; ++mi)
#pragma unroll
        for (int ni = 0; ni < 8; ++ni)
#pragma unroll
            for (int q = 0; q < 4; ++q) acc[mi][ni][q] = 0.f;

    int l15 = lane & 31 & 15, lkb = (lane >> 4) * 16;

#pragma unroll
    for (int c = 0; c < 4; ++c) {
        if (c < 3) asm volatile("cp.async.wait_group 1;" ::: "memory");
        else       asm volatile("cp.async.wait_group 0;" ::: "memory");
        __syncthreads();

        int buf = c & 1;
        bool a_smem = (c < 2) ? (A1S != 0) : (A2S != 0);
        uint32_t Ab;
        int arow;
        if (a_smem) {
            Ab = sb + TILE_OFF + (uint32_t)(wr * 32 + l15) * TT_ROW + lkb + (c & 1) * 128;
            arow = TT_ROW;
        } else {
            Ab = sb + buf * CH_BUF + (uint32_t)(wr * 32 + l15) * T_ROW + lkb;
            arow = T_ROW;
        }
        uint32_t Bb = sb + buf * CH_BUF + CH_B + (uint32_t)(wc * 64 + l15) * T_ROW + lkb;
#pragma unroll
        for (int s = 0; s < 4; ++s) {
            uint32_t Aks = Ab + s * 32;
            uint32_t Bks = Bb + s * 32;
            uint32_t A0[4], A1[4];
            ldmx4(A0, Aks);
            ldmx4(A1, Aks + 16 * arow);
            uint32_t B[4][4];
#pragma unroll
            for (int nb = 0; nb < 4; ++nb) ldmx4(B[nb], Bks + nb * (16 * T_ROW));
#pragma unroll
            for (int ni = 0; ni < 8; ++ni) {
                int nb = ni >> 1, hb = ni & 1;
                mma16816(acc[0][ni], A0, B[nb][hb], B[nb][2 + hb]);
                mma16816(acc[1][ni], A1, B[nb][hb], B[nb][2 + hb]);
            }
        }
        __syncthreads();
        if (c + 2 < 4) load_chunk(c + 2, buf);
    }

    // ---- epilogue ----
    int quad = lane >> 2, tq = lane & 3;
    if (OUT == 2) {
        // fp32 staging at offset 0 (chunk buffers are free), then coalesced stores
#pragma unroll
        for (int ni = 0; ni < 8; ++ni) {
            int cbase = wc * 64 + ni * 8 + tq * 2;
            float bv0 = __ldg(bias + cbase), bv1 = __ldg(bias + cbase + 1);
#pragma unroll
            for (int mi = 0; mi < 2; ++mi)
#pragma unroll
                for (int h = 0; h < 2; ++h) {
                    int row = wr * 32 + mi * 16 + quad + h * 8;
                    float x0 = acc[mi][ni][2 * h + 0] + bv0;
                    float x1 = acc[mi][ni][2 * h + 1] + bv1;
                    if (ACT == 1) { x0 = fmaxf(x0, 0.f); x1 = fmaxf(x1, 0.f); }
                    if (ACT == 2) { x0 = (x0 >= 0.f) ? x0 : 0.2f * x0;
                                    x1 = (x1 >= 0.f) ? x1 : 0.2f * x1; }
                    *(float2*)(smem + row * CF_ROW + cbase * 4) = make_float2(x0, x1);
                }
        }
        __syncthreads();
#pragma unroll
        for (int it = 0; it < 16; ++it) {
            int r = wid * 16 + it;
            int grow = mbrow + r;
            if (grow >= M) continue;
            float4 v = *(float4*)(smem + r * CF_ROW + lane * 16);
            *(float4*)(go32 + (size_t)grow * 128 + lane * 4) = v;
        }
    } else {
        // fp16 into the tile (becomes next pass's smem operand)
#pragma unroll
        for (int ni = 0; ni < 8; ++ni) {
            int cbase = wc * 64 + ni * 8 + tq * 2;
            float bv0 = __ldg(bias + cbase), bv1 = __ldg(bias + cbase + 1);
#pragma unroll
            for (int mi = 0; mi < 2; ++mi)
#pragma unroll
                for (int h = 0; h < 2; ++h) {
                    int row = wr * 32 + mi * 16 + quad + h * 8;
                    float x0 = acc[mi][ni][2 * h + 0] + bv0;
                    float x1 = acc[mi][ni][2 * h + 1] + bv1;
                    if (ACT == 1) { x0 = fmaxf(x0, 0.f); x1 = fmaxf(x1, 0.f); }
                    if (ACT == 2) { x0 = (x0 >= 0.f) ? x0 : 0.2f * x0;
                                    x1 = (x1 >= 0.f) ? x1 : 0.2f * x1; }
                    *(uint32_t*)(smem + TILE_OFF + row * TT_ROW + cbase * 2) =
                        packh(__float2half_rn(x0), __float2half_rn(x1));
                }
        }
        __syncthreads();
        if (OUT == 1) {
            int row2 = lane >> 4, colg = lane & 15;
#pragma unroll
            for (int it = 0; it < 8; ++it) {
                int r = wid * 16 + it * 2 + row2;
                int grow = mbrow + r;
                if (grow >= M) continue;
                uint4 v = *(uint4*)(smem + TILE_OFF + r * TT_ROW + colg * 16);
                *(uint4*)(go16 + (size_t)grow * 128 + colg * 8) = v;
            }
        }
    }
}

// ---------------- GEMM kernels ----------------
// stage0: ii2 = [ii ; ke] @ w4^T + b
__global__ void __launch_bounds__(256, 2) gemm1(
    const h16* __restrict__ a1, const h16* __restrict__ a2,
    const h16* __restrict__ w, const float* __restrict__ bias,
    h16* __restrict__ o, int M)
{
    extern __shared__ char smem[];
    uint32_t sb = s2u(smem);
    gpass<0, 0, 0, 1>(smem, sb, threadIdx.x, threadIdx.x & 31, threadIdx.x >> 5,
                      blockIdx.x * 128, M, a1, a2, w, bias, o, nullptr);
}

// F1 (belong): tmp=relu(ee,nb@W1); hiI=(tmp,nb)@Wf (smem+global); sc=(hiI,ee)@w1 (global)
__global__ void __launch_bounds__(256, 2) fused3_a(
    const h16* __restrict__ ee, const h16* __restrict__ nb,
    const h16* __restrict__ w0, const float* __restrict__ b0,
    const h16* __restrict__ w1, const float* __restrict__ b1,
    const h16* __restrict__ w2, const float* __restrict__ b2,
    h16* __restrict__ hiI, h16* __restrict__ sc, int M)
{
    extern __shared__ char smem[];
    uint32_t sb = s2u(smem);
    int tid = threadIdx.x, lane = tid & 31, wid = tid >> 5, mb = blockIdx.x * 128;
    gpass<0, 0, 1, 0>(smem, sb, tid, lane, wid, mb, M, ee, nb, w0, b0, nullptr, nullptr);
    gpass<1, 0, 0, 1>(smem, sb, tid, lane, wid, mb, M, nullptr, nb, w1, b1, hiI, nullptr);
    gpass<1, 0, 0, 1>(smem, sb, tid, lane, wid, mb, M, nullptr, ee, w2, b2, sc, nullptr);
}

// F2 (collab): tmp=relu(ee,nc@W4); hiS=(tmp,nc)@Wf (smem only); out=leaky((hiI,hiS)@comb) fp32
__global__ void __launch_bounds__(256, 2) fused3_b(
    const h16* __restrict__ ee, const h16* __restrict__ nc,
    const h16* __restrict__ w0, const float* __restrict__ b0,
    const h16* __restrict__ w1, const float* __restrict__ b1,
    const h16* __restrict__ hiI, const h16* __restrict__ w2,
    const float* __restrict__ b2, float* __restrict__ out, int M)
{
    extern __shared__ char smem[];
    uint32_t sb = s2u(smem);
    int tid = threadIdx.x, lane = tid & 31, wid = tid >> 5, mb = blockIdx.x * 128;
    gpass<0, 0, 1, 0>(smem, sb, tid, lane, wid, mb, M, ee, nc, w0, b0, nullptr, nullptr);
    gpass<1, 0, 0, 0>(smem, sb, tid, lane, wid, mb, M, nullptr, nc, w1, b1, nullptr, nullptr);
    gpass<0, 1, 2, 2>(smem, sb, tid, lane, wid, mb, M, hiI, nullptr, w2, b2, nullptr, out);
}

// ---------------- prep1: fp16 convert (ee/ii/ke) + fold_mats + fold_bias ----------------
__global__ void prep1(const float* __restrict__ e_emb, const float* __restrict__ ii,
                      const float* __restrict__ k_emb,
                      const float* __restrict__ w2W, const float* __restrict__ w2b,
                      const float* __restrict__ w3W, const float* __restrict__ w3b,
                      const float* __restrict__ ekS1, const float* __restrict__ ekN1,
                      const float* __restrict__ eeS1, const float* __restrict__ eeN1,
                      const float* __restrict__ ekb1, const float* __restrict__ eeb1) {
    int bid = blockIdx.x, tid = threadIdx.x;
    if (bid < 50000) {
        int i = bid * 256 + tid;
        g_ee[i] = __float2half_rn(e_emb[i]);
    } else if (bid < 55000) {
        int i = (bid - 50000) * 256 + tid;
        g_ii[i] = __float2half_rn(ii[i]);
    } else if (bid < 60000) {
        int i = (bid - 55000) * 256 + tid;
        g_ke[i] = __float2half_rn(k_emb[i]);
    } else if (bid < 60256) {                   // fold_mats: M = A @ B
        int lb = bid - 60000;
        int mat = lb >> 6;
        int idx = (lb & 63) * 256 + tid;
        const float* A = (mat < 2) ? w2W : w3W;
        const float* B = (mat == 0) ? ekS1 : (mat == 1) ? ekN1 : (mat == 2) ? eeS1 : eeN1;
        float* O = (mat == 0) ? g_M1 : (mat == 1) ? g_M2 : (mat == 2) ? g_M3 : g_M4;
        int n = idx >> 7, k = idx & 127;
        float acc = 0.f;
#pragma unroll 8
        for (int j = 0; j < 128; ++j)
            acc += A[n * 128 + j] * B[j * 128 + k];
        O[idx] = acc;
    } else {
        int t = tid;
        if (t < 128) {
            float a = 0.f, b = 0.f;
#pragma unroll 8
            for (int j = 0; j < 128; ++j) {
                a += w2W[t * 128 + j] * ekb1[j];
                b += w3W[t * 128 + j] * eeb1[j];
            }
            g_c1[t] = a + w2b[t];
            g_c2[t] = b + w3b[t];
        }
    }
}

// ---------------- prep2: fp16 convert all 7 stage weight matrices ----------------
__global__ void prep2(const float* __restrict__ w4W, const float* __restrict__ ek_self,
                      const float* __restrict__ ek_neigh, const float* __restrict__ w1W,
                      const float* __restrict__ ee_self, const float* __restrict__ ee_neigh,
                      const float* __restrict__ combW) {
    int bid = blockIdx.x;
    int stage = bid >> 7;
    int idx = (bid & 127) * 256 + threadIdx.x;
    const float* a; const float* b;
    switch (stage) {
        case 0: a = w4W;     b = nullptr;   break;
        case 1: a = ek_self; b = ek_neigh;  break;
        case 2: a = g_M1;    b = g_M2;      break;
        case 3: a = w1W;     b = nullptr;   break;
        case 4: a = ee_self; b = ee_neigh;  break;
        case 5: a = g_M3;    b = g_M4;      break;
        default: a = combW;  b = nullptr;   break;
    }
    int n = idx >> 8, k = idx & 255;
    float v = b ? (k < 128 ? a[n * 128 + k] : b[n * 128 + (k - 128)]) : a[idx];
    g_W[stage][idx] = __float2half_rn(v);
}

// ---------------- CSR build (both graphs via gridDim.y) ----------------
__global__ void zero_both() {
    int i = blockIdx.x * blockDim.x + threadIdx.x;
    if (i < NE) (blockIdx.y ? g_degC : g_degB)[i] = 0;
}
__global__ void count_both(const int* __restrict__ b_dst, const int* __restrict__ c_dst, int E) {
    int i = blockIdx.x * blockDim.x + threadIdx.x;
    if (i >= E) return;
    if (blockIdx.y) atomicAdd(&g_degC[c_dst[i]], 1);
    else            atomicAdd(&g_degB[b_dst[i]], 1);
}
__global__ void scanA() {
    __shared__ int ws[32];
    int g = blockIdx.y, tid = threadIdx.x, lane = tid & 31, wid = tid >> 5;
    int* deg = g ? g_degC : g_degB;
    int* rp  = g ? g_rpC  : g_rpB;
    int i = blockIdx.x * 1024 + tid;
    int v = (i < NE) ? deg[i] : 0;
    int inc = v;
#pragma unroll
    for (int o = 1; o < 32; o <<= 1) {
        int x = __shfl_up_sync(0xFFFFFFFFu, inc, o);
        if (lane >= o) inc += x;
    }
    if (lane == 31) ws[wid] = inc;
    __syncthreads();
    if (wid == 0) {
        int s = ws[lane];
#pragma unroll
        for (int o = 1; o < 32; o <<= 1) {
            int x = __shfl_up_sync(0xFFFFFFFFu, s, o);
            if (lane >= o) s += x;
        }
        ws[lane] = s;
    }
    __syncthreads();
    int off = wid ? ws[wid - 1] : 0;
    if (i < NE) rp[i] = off + inc - v;
    if (tid == 1023) g_part[g * 128 + blockIdx.x] = off + inc;
}
__global__ void scanB(int nblk) {
    __shared__ int ws[4];
    int g = blockIdx.y, tid = threadIdx.x, lane = tid & 31, wid = tid >> 5;
    int v = (tid < nblk) ? g_part[g * 128 + tid] : 0;
    int inc = v;
#pragma unroll
    for (int o = 1; o < 32; o <<= 1) {
        int x = __shfl_up_sync(0xFFFFFFFFu, inc, o);
        if (lane >= o) inc += x;
    }
    if (lane == 31) ws[wid] = inc;
    __syncthreads();
    int woff = 0;
    for (int w = 0; w < wid; ++w) woff += ws[w];
    int excl = woff + inc - v;
    if (tid < nblk) g_part[g * 128 + tid] = excl;
    if (tid == nblk - 1) (g ? g_rpC : g_rpB)[NE] = excl + v;
}
__global__ void scanC() {
    int g = blockIdx.y;
    int i = blockIdx.x * 1024 + threadIdx.x;
    if (i >= NE) return;
    int* rp  = g ? g_rpC  : g_rpB;
    int* cur = g ? g_curC : g_curB;
    int val = rp[i] + g_part[g * 128 + blockIdx.x];
    rp[i] = val;
    cur[i] = val;
}
__global__ void scatter_both(const int* __restrict__ b_src, const int* __restrict__ b_dst,
                             const int* __restrict__ c_src, const int* __restrict__ c_dst,
                             const float* __restrict__ cf_ew, int E) {
    int i = blockIdx.x * blockDim.x + threadIdx.x;
    if (i >= E) return;
    if (blockIdx.y) {
        int pos = atomicAdd(&g_curC[c_dst[i]], 1);
        g_esrcC[pos] = c_src[i];
        g_ewC[pos] = cf_ew[i];
    } else {
        int pos = atomicAdd(&g_curB[b_dst[i]], 1);
        g_esrcB[pos] = b_src[i];
    }
}

// ---------------- mean aggregation (fp16 plane, fp32 accum): warp per destination ----------------
template <int WEIGHTED>
__global__ void aggregate_kernel(const h16* __restrict__ sh, h16* __restrict__ oh,
                                 const int* __restrict__ rowptr, const int* __restrict__ esrc,
                                 const float* __restrict__ ew, int n) {
    int gw = (blockIdx.x * blockDim.x + threadIdx.x) >> 5;
    int lane = threadIdx.x & 31;
    if (gw >= n) return;
    int s0 = rowptr[gw], s1 = rowptr[gw + 1];
    float a0 = 0.f, a1 = 0.f, a2 = 0.f, a3 = 0.f;
    for (int j = s0; j < s1; ++j) {
        int sidx = esrc[j];
        uint2 u = *(const uint2*)(sh + (size_t)sidx * D + lane * 4);
        float w = WEIGHTED ? ew[j] : 1.0f;
        a0 += hlo(u.x) * w;
        a1 += hhi(u.x) * w;
        a2 += hlo(u.y) * w;
        a3 += hhi(u.y) * w;
    }
    float inv = 1.0f / fmaxf((float)(s1 - s0), 1.0f);
    a0 *= inv; a1 *= inv; a2 *= inv; a3 *= inv;
    *(uint2*)(oh + (size_t)gw * D + lane * 4) =
        make_uint2(packh(__float2half_rn(a0), __float2half_rn(a1)),
                   packh(__float2half_rn(a2), __float2half_rn(a3)));
}

// ---------------- launch ----------------
extern "C" void kernel_launch(void* const* d_in, const int* in_sizes, int n_in,
                              void* d_out, int out_size) {
    const float* ii      = (const float*)d_in[0];
    const float* e_emb   = (const float*)d_in[1];
    const float* k_emb   = (const float*)d_in[2];
    const float* cf_ew   = (const float*)d_in[3];
    const int*   b_src   = (const int*)d_in[4];
    const int*   b_dst   = (const int*)d_in[5];
    const int*   c_src   = (const int*)d_in[6];
    const int*   c_dst   = (const int*)d_in[7];
    const float* ek_self = (const float*)d_in[8];
    const float* ek_neigh= (const float*)d_in[9];
    const float* ek_bias = (const float*)d_in[10];
    const float* ee_self = (const float*)d_in[11];
    const float* ee_neigh= (const float*)d_in[12];
    const float* ee_bias = (const float*)d_in[13];
    const float* w1W = (const float*)d_in[14];
    const float* w1b = (const float*)d_in[15];
    const float* w2W = (const float*)d_in[16];
    const float* w2b = (const float*)d_in[17];
    const float* w3W = (const float*)d_in[18];
    const float* w3b = (const float*)d_in[19];
    const float* w4W = (const float*)d_in[20];
    const float* w4b = (const float*)d_in[21];
    const float* combW = (const float*)d_in[22];
    const float* combb = (const float*)d_in[23];
    float* out = (float*)d_out;

    int n_k = in_sizes[0] / D;
    int n_e = in_sizes[1] / D;
    int E   = in_sizes[4];

    h16 *ee, *iip, *ke, *ii2, *nb, *nc, *hiI, *sc, *W;
    float *p_c1, *p_c2, *p_ewC;
    int *p_rpB, *p_rpC, *p_esB, *p_esC;
    cudaGetSymbolAddress((void**)&ee,  g_ee);
    cudaGetSymbolAddress((void**)&iip, g_ii);
    cudaGetSymbolAddress((void**)&ke,  g_ke);
    cudaGetSymbolAddress((void**)&ii2, g_ii2);
    cudaGetSymbolAddress((void**)&nb,  g_nb);
    cudaGetSymbolAddress((void**)&nc,  g_nc);
    cudaGetSymbolAddress((void**)&hiI, g_hiI);
    cudaGetSymbolAddress((void**)&sc,  g_sc);
    cudaGetSymbolAddress((void**)&W,   g_W);
    cudaGetSymbolAddress((void**)&p_c1, g_c1);   cudaGetSymbolAddress((void**)&p_c2, g_c2);
    cudaGetSymbolAddress((void**)&p_rpB, g_rpB); cudaGetSymbolAddress((void**)&p_rpC, g_rpC);
    cudaGetSymbolAddress((void**)&p_esB, g_esrcB); cudaGetSymbolAddress((void**)&p_esC, g_esrcC);
    cudaGetSymbolAddress((void**)&p_ewC, g_ewC);

    cudaFuncSetAttribute(gemm1,    cudaFuncAttributeMaxDynamicSharedMemorySize, SM_TOTAL);
    cudaFuncSetAttribute(fused3_a, cudaFuncAttributeMaxDynamicSharedMemorySize, SM_TOTAL);
    cudaFuncSetAttribute(fused3_b, cudaFuncAttributeMaxDynamicSharedMemorySize, SM_TOTAL);

    int gE   = (E + 255) / 256;
    int gNe  = (n_e + 255) / 256;
    int gSc  = (n_e + 1023) / 1024;
    int gAgg = (n_e * 32 + 255) / 256;
    int gbK  = (n_k + 127) / 128;
    int gbE  = (n_e + 127) / 128;

    // prep
    prep1<<<60257, 256>>>(e_emb, ii, k_emb, w2W, w2b, w3W, w3b,
                          ek_self + DD, ek_neigh + DD, ee_self + DD, ee_neigh + DD,
                          ek_bias + D, ee_bias + D);
    prep2<<<7 * 128, 256>>>(w4W, ek_self, ek_neigh, w1W, ee_self, ee_neigh, combW);
    // CSR (both graphs)
    zero_both<<<dim3(gNe, 2), 256>>>();
    count_both<<<dim3(gE, 2), 256>>>(b_dst, c_dst, E);
    scanA<<<dim3(gSc, 2), 1024>>>();
    // ii2 = [ii ; k_emb] @ w4^T + w4_b
    gemm1<<<gbK, 256, SM_TOTAL>>>(iip, ke, W + 0*32768, w4b, ii2, n_k);
    scanB<<<dim3(1, 2), 128>>>(gSc);
    scanC<<<dim3(gSc, 2), 1024>>>();
    scatter_both<<<dim3(gE, 2), 256>>>(b_src, b_dst, c_src, c_dst, cf_ew, E);
    // belong mean aggregation (shared by both layers)
    aggregate_kernel<0><<<gAgg, 256>>>(ii2, nb, p_rpB, p_esB, nullptr, n_e);
    // F1: belong layer0+layer1(+w2 folded) + src_com stage, fused
    fused3_a<<<gbE, 256, SM_TOTAL>>>(ee, nb, W + 1*32768, ek_bias,
                                     W + 2*32768, p_c1, W + 3*32768, w1b,
                                     hiI, sc, n_e);
    // collab weighted mean aggregation
    aggregate_kernel<1><<<gAgg, 256>>>(sc, nc, p_rpC, p_esC, p_ewC, n_e);
    // F2: collab layer0+layer1(+w3 folded) + comb stage, fused -> fp32 out
    fused3_b<<<gbE, 256, SM_TOTAL>>>(ee, nc, W + 4*32768, ee_bias,
                                     W + 5*32768, p_c2, hiI, W + 6*32768,
                                     combb, out, n_e);
}

// round 8
// speedup vs baseline: 3.7425x; 1.0403x over previous
#include <cuda_runtime.h>
#include <cuda_fp16.h>
#include <cstdint>

typedef __half h16;
#define NK   10000
#define NE   100000
#define D    128
#define DD   (128*128)
#define EDG  1600000

// ---------------- scratch (static __device__ — no allocations allowed) ----------------
__device__ __align__(16) h16 g_ee[NE*D];
__device__ __align__(16) h16 g_ii[NK*D];
__device__ __align__(16) h16 g_ke[NK*D];
__device__ __align__(16) h16 g_ii2[NK*D];
__device__ __align__(16) h16 g_nb[NE*D];
__device__ __align__(16) h16 g_nc[NE*D];
__device__ __align__(16) h16 g_hiI[NE*D];
__device__ __align__(16) h16 g_sc[NE*D];
__device__ __align__(16) h16 g_W[7][128*256];       // per stage [128 n][256 k]
__device__ __align__(16) float g_M1[DD], g_M2[DD], g_M3[DD], g_M4[DD];
__device__ __align__(16) float g_c1[D], g_c2[D];
// CSR (B = belong, C = collab)
__device__ __align__(16) int   g_degB[NE], g_degC[NE];
__device__ __align__(16) int   g_rpB[NE+1], g_rpC[NE+1];
__device__ __align__(16) int   g_curB[NE], g_curC[NE];
__device__ __align__(16) int   g_esrcB[EDG], g_esrcC[EDG];
__device__ __align__(16) float g_ewC[EDG];
__device__ __align__(16) int   g_part[2*128];

// ---------------- host-side aux (streams/events created once, before checkpoints) ----
struct Aux {
    cudaStream_t s2, s3;
    cudaEvent_t evF, evJ2, evJ3;
    Aux() {
        cudaStreamCreateWithFlags(&s2, cudaStreamNonBlocking);
        cudaStreamCreateWithFlags(&s3, cudaStreamNonBlocking);
        cudaEventCreateWithFlags(&evF,  cudaEventDisableTiming);
        cudaEventCreateWithFlags(&evJ2, cudaEventDisableTiming);
        cudaEventCreateWithFlags(&evJ3, cudaEventDisableTiming);
    }
};
static Aux g_aux;

// ---------------- small helpers ----------------
__device__ __forceinline__ uint32_t s2u(const void* p) {
    uint32_t a;
    asm("{ .reg .u64 t; cvta.to.shared.u64 t, %1; cvt.u32.u64 %0, t; }" : "=r"(a) : "l"(p));
    return a;
}
__device__ __forceinline__ uint32_t packh(h16 a, h16 b) {
    return ((uint32_t)__half_as_ushort(b) << 16) | (uint32_t)__half_as_ushort(a);
}
__device__ __forceinline__ float hlo(uint32_t u) {
    return __half2float(__ushort_as_half((unsigned short)(u & 0xFFFF)));
}
__device__ __forceinline__ float hhi(uint32_t u) {
    return __half2float(__ushort_as_half((unsigned short)(u >> 16)));
}
__device__ __forceinline__ void ldmx4(uint32_t* r, uint32_t addr) {
    asm volatile("ldmatrix.sync.aligned.m8n8.x4.shared.b16 {%0,%1,%2,%3}, [%4];"
                 : "=r"(r[0]), "=r"(r[1]), "=r"(r[2]), "=r"(r[3]) : "r"(addr));
}
__device__ __forceinline__ void mma16816(float* c, const uint32_t* a, uint32_t b0, uint32_t b1) {
    asm volatile("mma.sync.aligned.m16n8k16.row.col.f32.f16.f16.f32 "
                 "{%0,%1,%2,%3}, {%4,%5,%6,%7}, {%8,%9}, {%0,%1,%2,%3};"
                 : "+f"(c[0]), "+f"(c[1]), "+f"(c[2]), "+f"(c[3])
                 : "r"(a[0]), "r"(a[1]), "r"(a[2]), "r"(a[3]), "r"(b0), "r"(b1));
}
__device__ __forceinline__ void cp16(uint32_t s, const void* g) {
    asm volatile("cp.async.cg.shared.global [%0], [%1], 16;" :: "r"(s), "l"(g));
}

// ---------------- SMEM layout ----------------
#define T_ROW    144
#define CH_B     18432
#define CH_BUF   36864
#define TILE_OFF 73728
#define TT_ROW   272
#define SM_TOTAL 108544
#define CF_ROW   528

// ---------------- generic GEMM pass (identical to R7) ----------------
template <int A1S, int A2S, int ACT, int OUT>
__device__ __forceinline__ void gpass(
    char* smem, uint32_t sb, int tid, int lane, int wid, int mbrow, int M,
    const h16* gA1, const h16* gA2, const h16* w, const float* bias,
    h16* go16, float* go32)
{
    int wr = wid & 3, wc = wid >> 2;

    auto load_chunk = [&](int c, int buf) {
        int k0 = (c & 1) * 64;
        bool a_smem = (c < 2) ? (A1S != 0) : (A2S != 0);
        const h16* A = (c < 2) ? gA1 : gA2;
        if (!a_smem) {
#pragma unroll
            for (int u = 0; u < 4; ++u) {
                int i = u * 256 + tid;
                int row = i >> 3, g = i & 7;
                int grow = mbrow + row;
                if (grow < M)
                    cp16(sb + buf * CH_BUF + row * T_ROW + g * 16,
                         A + (size_t)grow * 128 + k0 + g * 8);
            }
        }
#pragma unroll
        for (int u = 0; u < 4; ++u) {
            int i = u * 256 + tid;
            int n = i >> 3, g = i & 7;
            cp16(sb + buf * CH_BUF + CH_B + n * T_ROW + g * 16,
                 w + n * 256 + c * 64 + g * 8);
        }
        asm volatile("cp.async.commit_group;" ::: "memory");
    };

    load_chunk(0, 0);
    load_chunk(1, 1);

    float acc[2][8][4];
#pragma unroll
    for (int mi = 0; mi < 2; ++mi)
#pragma unroll
        for (int ni = 0; ni < 8; ++ni)
#pragma unroll
            for (int q = 0; q < 4; ++q) acc[mi][ni][q] = 0.f;

    int l15 = lane & 15, lkb = (lane >> 4) * 16;

#pragma unroll
    for (int c = 0; c < 4; ++c) {
        if (c < 3) asm volatile("cp.async.wait_group 1;" ::: "memory");
        else       asm volatile("cp.async.wait_group 0;" ::: "memory");
        __syncthreads();

        int buf = c & 1;
        bool a_smem = (c < 2) ? (A1S != 0) : (A2S != 0);
        uint32_t Ab;
        int arow;
        if (a_smem) {
            Ab = sb + TILE_OFF + (uint32_t)(wr * 32 + l15) * TT_ROW + lkb + (c & 1) * 128;
            arow = TT_ROW;
        } else {
            Ab = sb + buf * CH_BUF + (uint32_t)(wr * 32 + l15) * T_ROW + lkb;
            arow = T_ROW;
        }
        uint32_t Bb = sb + buf * CH_BUF + CH_B + (uint32_t)(wc * 64 + l15) * T_ROW + lkb;
#pragma unroll
        for (int s = 0; s < 4; ++s) {
            uint32_t Aks = Ab + s * 32;
            uint32_t Bks = Bb + s * 32;
            uint32_t A0[4], A1[4];
            ldmx4(A0, Aks);
            ldmx4(A1, Aks + 16 * arow);
            uint32_t B[4][4];
#pragma unroll
            for (int nb = 0; nb < 4; ++nb) ldmx4(B[nb], Bks + nb * (16 * T_ROW));
#pragma unroll
            for (int ni = 0; ni < 8; ++ni) {
                int nb = ni >> 1, hb = ni & 1;
                mma16816(acc[0][ni], A0, B[nb][hb], B[nb][2 + hb]);
                mma16816(acc[1][ni], A1, B[nb][hb], B[nb][2 + hb]);
            }
        }
        __syncthreads();
        if (c + 2 < 4) load_chunk(c + 2, buf);
    }

    int quad = lane >> 2, tq = lane & 3;
    if (OUT == 2) {
#pragma unroll
        for (int ni = 0; ni < 8; ++ni) {
            int cbase = wc * 64 + ni * 8 + tq * 2;
            float bv0 = __ldg(bias + cbase), bv1 = __ldg(bias + cbase + 1);
#pragma unroll
            for (int mi = 0; mi < 2; ++mi)
#pragma unroll
                for (int h = 0; h < 2; ++h) {
                    int row = wr * 32 + mi * 16 + quad + h * 8;
                    float x0 = acc[mi][ni][2 * h + 0] + bv0;
                    float x1 = acc[mi][ni][2 * h + 1] + bv1;
                    if (ACT == 1) { x0 = fmaxf(x0, 0.f); x1 = fmaxf(x1, 0.f); }
                    if (ACT == 2) { x0 = (x0 >= 0.f) ? x0 : 0.2f * x0;
                                    x1 = (x1 >= 0.f) ? x1 : 0.2f * x1; }
                    *(float2*)(smem + row * CF_ROW + cbase * 4) = make_float2(x0, x1);
                }
        }
        __syncthreads();
#pragma unroll
        for (int it = 0; it < 16; ++it) {
            int r = wid * 16 + it;
            int grow = mbrow + r;
            if (grow >= M) continue;
            float4 v = *(float4*)(smem + r * CF_ROW + lane * 16);
            *(float4*)(go32 + (size_t)grow * 128 + lane * 4) = v;
        }
    } else {
#pragma unroll
        for (int ni = 0; ni < 8; ++ni) {
            int cbase = wc * 64 + ni * 8 + tq * 2;
            float bv0 = __ldg(bias + cbase), bv1 = __ldg(bias + cbase + 1);
#pragma unroll
            for (int mi = 0; mi < 2; ++mi)
#pragma unroll
                for (int h = 0; h < 2; ++h) {
                    int row = wr * 32 + mi * 16 + quad + h * 8;
                    float x0 = acc[mi][ni][2 * h + 0] + bv0;
                    float x1 = acc[mi][ni][2 * h + 1] + bv1;
                    if (ACT == 1) { x0 = fmaxf(x0, 0.f); x1 = fmaxf(x1, 0.f); }
                    if (ACT == 2) { x0 = (x0 >= 0.f) ? x0 : 0.2f * x0;
                                    x1 = (x1 >= 0.f) ? x1 : 0.2f * x1; }
                    *(uint32_t*)(smem + TILE_OFF + row * TT_ROW + cbase * 2) =
                        packh(__float2half_rn(x0), __float2half_rn(x1));
                }
        }
        __syncthreads();
        if (OUT == 1) {
            int row2 = lane >> 4, colg = lane & 15;
#pragma unroll
            for (int it = 0; it < 8; ++it) {
                int r = wid * 16 + it * 2 + row2;
                int grow = mbrow + r;
                if (grow >= M) continue;
                uint4 v = *(uint4*)(smem + TILE_OFF + r * TT_ROW + colg * 16);
                *(uint4*)(go16 + (size_t)grow * 128 + colg * 8) = v;
            }
        }
    }
}

// ---------------- GEMM kernels ----------------
__global__ void __launch_bounds__(256, 2) gemm1(
    const h16* __restrict__ a1, const h16* __restrict__ a2,
    const h16* __restrict__ w, const float* __restrict__ bias,
    h16* __restrict__ o, int M)
{
    extern __shared__ char smem[];
    uint32_t sb = s2u(smem);
    gpass<0, 0, 0, 1>(smem, sb, threadIdx.x, threadIdx.x & 31, threadIdx.x >> 5,
                      blockIdx.x * 128, M, a1, a2, w, bias, o, nullptr);
}

__global__ void __launch_bounds__(256, 2) fused3_a(
    const h16* __restrict__ ee, const h16* __restrict__ nb,
    const h16* __restrict__ w0, const float* __restrict__ b0,
    const h16* __restrict__ w1, const float* __restrict__ b1,
    const h16* __restrict__ w2, const float* __restrict__ b2,
    h16* __restrict__ hiI, h16* __restrict__ sc, int M)
{
    extern __shared__ char smem[];
    uint32_t sb = s2u(smem);
    int tid = threadIdx.x, lane = tid & 31, wid = tid >> 5, mb = blockIdx.x * 128;
    gpass<0, 0, 1, 0>(smem, sb, tid, lane, wid, mb, M, ee, nb, w0, b0, nullptr, nullptr);
    gpass<1, 0, 0, 1>(smem, sb, tid, lane, wid, mb, M, nullptr, nb, w1, b1, hiI, nullptr);
    gpass<1, 0, 0, 1>(smem, sb, tid, lane, wid, mb, M, nullptr, ee, w2, b2, sc, nullptr);
}

__global__ void __launch_bounds__(256, 2) fused3_b(
    const h16* __restrict__ ee, const h16* __restrict__ nc,
    const h16* __restrict__ w0, const float* __restrict__ b0,
    const h16* __restrict__ w1, const float* __restrict__ b1,
    const h16* __restrict__ hiI, const h16* __restrict__ w2,
    const float* __restrict__ b2, float* __restrict__ out, int M)
{
    extern __shared__ char smem[];
    uint32_t sb = s2u(smem);
    int tid = threadIdx.x, lane = tid & 31, wid = tid >> 5, mb = blockIdx.x * 128;
    gpass<0, 0, 1, 0>(smem, sb, tid, lane, wid, mb, M, ee, nc, w0, b0, nullptr, nullptr);
    gpass<1, 0, 0, 0>(smem, sb, tid, lane, wid, mb, M, nullptr, nc, w1, b1, nullptr, nullptr);
    gpass<0, 1, 2, 2>(smem, sb, tid, lane, wid, mb, M, hiI, nullptr, w2, b2, nullptr, out);
}

// ---------------- prep1 / prep2 (identical to R7) ----------------
__global__ void prep1(const float* __restrict__ e_emb, const float* __restrict__ ii,
                      const float* __restrict__ k_emb,
                      const float* __restrict__ w2W, const float* __restrict__ w2b,
                      const float* __restrict__ w3W, const float* __restrict__ w3b,
                      const float* __restrict__ ekS1, const float* __restrict__ ekN1,
                      const float* __restrict__ eeS1, const float* __restrict__ eeN1,
                      const float* __restrict__ ekb1, const float* __restrict__ eeb1) {
    int bid = blockIdx.x, tid = threadIdx.x;
    if (bid < 50000) {
        int i = bid * 256 + tid;
        g_ee[i] = __float2half_rn(e_emb[i]);
    } else if (bid < 55000) {
        int i = (bid - 50000) * 256 + tid;
        g_ii[i] = __float2half_rn(ii[i]);
    } else if (bid < 60000) {
        int i = (bid - 55000) * 256 + tid;
        g_ke[i] = __float2half_rn(k_emb[i]);
    } else if (bid < 60256) {
        int lb = bid - 60000;
        int mat = lb >> 6;
        int idx = (lb & 63) * 256 + tid;
        const float* A = (mat < 2) ? w2W : w3W;
        const float* B = (mat == 0) ? ekS1 : (mat == 1) ? ekN1 : (mat == 2) ? eeS1 : eeN1;
        float* O = (mat == 0) ? g_M1 : (mat == 1) ? g_M2 : (mat == 2) ? g_M3 : g_M4;
        int n = idx >> 7, k = idx & 127;
        float acc = 0.f;
#pragma unroll 8
        for (int j = 0; j < 128; ++j)
            acc += A[n * 128 + j] * B[j * 128 + k];
        O[idx] = acc;
    } else {
        int t = tid;
        if (t < 128) {
            float a = 0.f, b = 0.f;
#pragma unroll 8
            for (int j = 0; j < 128; ++j) {
                a += w2W[t * 128 + j] * ekb1[j];
                b += w3W[t * 128 + j] * eeb1[j];
            }
            g_c1[t] = a + w2b[t];
            g_c2[t] = b + w3b[t];
        }
    }
}

__global__ void prep2(const float* __restrict__ w4W, const float* __restrict__ ek_self,
                      const float* __restrict__ ek_neigh, const float* __restrict__ w1W,
                      const float* __restrict__ ee_self, const float* __restrict__ ee_neigh,
                      const float* __restrict__ combW) {
    int bid = blockIdx.x;
    int stage = bid >> 7;
    int idx = (bid & 127) * 256 + threadIdx.x;
    const float* a; const float* b;
    switch (stage) {
        case 0: a = w4W;     b = nullptr;   break;
        case 1: a = ek_self; b = ek_neigh;  break;
        case 2: a = g_M1;    b = g_M2;      break;
        case 3: a = w1W;     b = nullptr;   break;
        case 4: a = ee_self; b = ee_neigh;  break;
        case 5: a = g_M3;    b = g_M4;      break;
        default: a = combW;  b = nullptr;   break;
    }
    int n = idx >> 8, k = idx & 255;
    float v = b ? (k < 128 ? a[n * 128 + k] : b[n * 128 + (k - 128)]) : a[idx];
    g_W[stage][idx] = __float2half_rn(v);
}

// ---------------- CSR build (per-graph parameterized) ----------------
__global__ void zero_k(int* __restrict__ deg) {
    int i = blockIdx.x * blockDim.x + threadIdx.x;
    if (i < NE) deg[i] = 0;
}
__global__ void count_k(const int* __restrict__ dst, int* __restrict__ deg, int E) {
    int i = blockIdx.x * blockDim.x + threadIdx.x;
    if (i < E) atomicAdd(&deg[dst[i]], 1);
}
__global__ void scanA_k(const int* __restrict__ deg, int* __restrict__ rp,
                        int* __restrict__ part) {
    __shared__ int ws[32];
    int tid = threadIdx.x, lane = tid & 31, wid = tid >> 5;
    int i = blockIdx.x * 1024 + tid;
    int v = (i < NE) ? deg[i] : 0;
    int inc = v;
#pragma unroll
    for (int o = 1; o < 32; o <<= 1) {
        int x = __shfl_up_sync(0xFFFFFFFFu, inc, o);
        if (lane >= o) inc += x;
    }
    if (lane == 31) ws[wid] = inc;
    __syncthreads();
    if (wid == 0) {
        int s = ws[lane];
#pragma unroll
        for (int o = 1; o < 32; o <<= 1) {
            int x = __shfl_up_sync(0xFFFFFFFFu, s, o);
            if (lane >= o) s += x;
        }
        ws[lane] = s;
    }
    __syncthreads();
    int off = wid ? ws[wid - 1] : 0;
    if (i < NE) rp[i] = off + inc - v;
    if (tid == 1023) part[blockIdx.x] = off + inc;
}
__global__ void scanB_k(int* __restrict__ part, int* __restrict__ rp, int nblk) {
    __shared__ int ws[4];
    int tid = threadIdx.x, lane = tid & 31, wid = tid >> 5;
    int v = (tid < nblk) ? part[tid] : 0;
    int inc = v;
#pragma unroll
    for (int o = 1; o < 32; o <<= 1) {
        int x = __shfl_up_sync(0xFFFFFFFFu, inc, o);
        if (lane >= o) inc += x;
    }
    if (lane == 31) ws[wid] = inc;
    __syncthreads();
    int woff = 0;
    for (int w = 0; w < wid; ++w) woff += ws[w];
    int excl = woff + inc - v;
    if (tid < nblk) part[tid] = excl;
    if (tid == nblk - 1) rp[NE] = excl + v;
}
__global__ void scanC_k(int* __restrict__ rp, int* __restrict__ cur,
                        const int* __restrict__ part) {
    int i = blockIdx.x * 1024 + threadIdx.x;
    if (i >= NE) return;
    int val = rp[i] + part[blockIdx.x];
    rp[i] = val;
    cur[i] = val;
}
template <int WEIGHTED>
__global__ void scatter_k(const int* __restrict__ src, const int* __restrict__ dst,
                          const float* __restrict__ ewin, int* __restrict__ cur,
                          int* __restrict__ esrc, float* __restrict__ ewout, int E) {
    int i = blockIdx.x * blockDim.x + threadIdx.x;
    if (i >= E) return;
    int pos = atomicAdd(&cur[dst[i]], 1);
    esrc[pos] = src[i];
    if (WEIGHTED) ewout[pos] = ewin[i];
}

// ---------------- mean aggregation (identical to R7) ----------------
template <int WEIGHTED>
__global__ void aggregate_kernel(const h16* __restrict__ sh, h16* __restrict__ oh,
                                 const int* __restrict__ rowptr, const int* __restrict__ esrc,
                                 const float* __restrict__ ew, int n) {
    int gw = (blockIdx.x * blockDim.x + threadIdx.x) >> 5;
    int lane = threadIdx.x & 31;
    if (gw >= n) return;
    int s0 = rowptr[gw], s1 = rowptr[gw + 1];
    float a0 = 0.f, a1 = 0.f, a2 = 0.f, a3 = 0.f;
    for (int j = s0; j < s1; ++j) {
        int sidx = esrc[j];
        uint2 u = *(const uint2*)(sh + (size_t)sidx * D + lane * 4);
        float w = WEIGHTED ? ew[j] : 1.0f;
        a0 += hlo(u.x) * w;
        a1 += hhi(u.x) * w;
        a2 += hlo(u.y) * w;
        a3 += hhi(u.y) * w;
    }
    float inv = 1.0f / fmaxf((float)(s1 - s0), 1.0f);
    a0 *= inv; a1 *= inv; a2 *= inv; a3 *= inv;
    *(uint2*)(oh + (size_t)gw * D + lane * 4) =
        make_uint2(packh(__float2half_rn(a0), __float2half_rn(a1)),
                   packh(__float2half_rn(a2), __float2half_rn(a3)));
}

// ---------------- launch ----------------
extern "C" void kernel_launch(void* const* d_in, const int* in_sizes, int n_in,
                              void* d_out, int out_size) {
    const float* ii      = (const float*)d_in[0];
    const float* e_emb   = (const float*)d_in[1];
    const float* k_emb   = (const float*)d_in[2];
    const float* cf_ew   = (const float*)d_in[3];
    const int*   b_src   = (const int*)d_in[4];
    const int*   b_dst   = (const int*)d_in[5];
    const int*   c_src   = (const int*)d_in[6];
    const int*   c_dst   = (const int*)d_in[7];
    const float* ek_self = (const float*)d_in[8];
    const float* ek_neigh= (const float*)d_in[9];
    const float* ek_bias = (const float*)d_in[10];
    const float* ee_self = (const float*)d_in[11];
    const float* ee_neigh= (const float*)d_in[12];
    const float* ee_bias = (const float*)d_in[13];
    const float* w1W = (const float*)d_in[14];
    const float* w1b = (const float*)d_in[15];
    const float* w2W = (const float*)d_in[16];
    const float* w2b = (const float*)d_in[17];
    const float* w3W = (const float*)d_in[18];
    const float* w3b = (const float*)d_in[19];
    const float* w4W = (const float*)d_in[20];
    const float* w4b = (const float*)d_in[21];
    const float* combW = (const float*)d_in[22];
    const float* combb = (const float*)d_in[23];
    float* out = (float*)d_out;

    int n_k = in_sizes[0] / D;
    int n_e = in_sizes[1] / D;
    int E   = in_sizes[4];

    h16 *ee, *iip, *ke, *ii2, *nb, *nc, *hiI, *sc, *W;
    float *p_c1, *p_c2, *p_ewC;
    int *p_rpB, *p_rpC, *p_esB, *p_esC, *p_degB, *p_degC, *p_curB, *p_curC, *p_part;
    cudaGetSymbolAddress((void**)&ee,  g_ee);
    cudaGetSymbolAddress((void**)&iip, g_ii);
    cudaGetSymbolAddress((void**)&ke,  g_ke);
    cudaGetSymbolAddress((void**)&ii2, g_ii2);
    cudaGetSymbolAddress((void**)&nb,  g_nb);
    cudaGetSymbolAddress((void**)&nc,  g_nc);
    cudaGetSymbolAddress((void**)&hiI, g_hiI);
    cudaGetSymbolAddress((void**)&sc,  g_sc);
    cudaGetSymbolAddress((void**)&W,   g_W);
    cudaGetSymbolAddress((void**)&p_c1, g_c1);   cudaGetSymbolAddress((void**)&p_c2, g_c2);
    cudaGetSymbolAddress((void**)&p_rpB, g_rpB); cudaGetSymbolAddress((void**)&p_rpC, g_rpC);
    cudaGetSymbolAddress((void**)&p_esB, g_esrcB); cudaGetSymbolAddress((void**)&p_esC, g_esrcC);
    cudaGetSymbolAddress((void**)&p_ewC, g_ewC);
    cudaGetSymbolAddress((void**)&p_degB, g_degB); cudaGetSymbolAddress((void**)&p_degC, g_degC);
    cudaGetSymbolAddress((void**)&p_curB, g_curB); cudaGetSymbolAddress((void**)&p_curC, g_curC);
    cudaGetSymbolAddress((void**)&p_part, g_part);

    cudaFuncSetAttribute(gemm1,    cudaFuncAttributeMaxDynamicSharedMemorySize, SM_TOTAL);
    cudaFuncSetAttribute(fused3_a, cudaFuncAttributeMaxDynamicSharedMemorySize, SM_TOTAL);
    cudaFuncSetAttribute(fused3_b, cudaFuncAttributeMaxDynamicSharedMemorySize, SM_TOTAL);

    int gE   = (E + 255) / 256;
    int gNe  = (n_e + 255) / 256;
    int gSc  = (n_e + 1023) / 1024;
    int gAgg = (n_e * 32 + 255) / 256;
    int gbK  = (n_k + 127) / 128;
    int gbE  = (n_e + 127) / 128;

    // ---- fork: CSR chains run concurrently with prep/gemm1 ----
    cudaEventRecord(g_aux.evF, 0);
    cudaStreamWaitEvent(g_aux.s2, g_aux.evF, 0);
    cudaStreamWaitEvent(g_aux.s3, g_aux.evF, 0);

    // s2: belong CSR
    zero_k<<<gNe, 256, 0, g_aux.s2>>>(p_degB);
    count_k<<<gE, 256, 0, g_aux.s2>>>(b_dst, p_degB, E);
    scanA_k<<<gSc, 1024, 0, g_aux.s2>>>(p_degB, p_rpB, p_part);
    scanB_k<<<1, 128, 0, g_aux.s2>>>(p_part, p_rpB, gSc);
    scanC_k<<<gSc, 1024, 0, g_aux.s2>>>(p_rpB, p_curB, p_part);
    scatter_k<0><<<gE, 256, 0, g_aux.s2>>>(b_src, b_dst, nullptr, p_curB, p_esB, nullptr, E);
    cudaEventRecord(g_aux.evJ2, g_aux.s2);

    // s3: collab CSR
    zero_k<<<gNe, 256, 0, g_aux.s3>>>(p_degC);
    count_k<<<gE, 256, 0, g_aux.s3>>>(c_dst, p_degC, E);
    scanA_k<<<gSc, 1024, 0, g_aux.s3>>>(p_degC, p_rpC, p_part + 128);
    scanB_k<<<1, 128, 0, g_aux.s3>>>(p_part + 128, p_rpC, gSc);
    scanC_k<<<gSc, 1024, 0, g_aux.s3>>>(p_rpC, p_curC, p_part + 128);
    scatter_k<1><<<gE, 256, 0, g_aux.s3>>>(c_src, c_dst, cf_ew, p_curC, p_esC, p_ewC, E);
    cudaEventRecord(g_aux.evJ3, g_aux.s3);

    // main stream: prep + stage0 GEMM (overlaps with CSR)
    prep1<<<60257, 256>>>(e_emb, ii, k_emb, w2W, w2b, w3W, w3b,
                          ek_self + DD, ek_neigh + DD, ee_self + DD, ee_neigh + DD,
                          ek_bias + D, ee_bias + D);
    prep2<<<7 * 128, 256>>>(w4W, ek_self, ek_neigh, w1W, ee_self, ee_neigh, combW);
    gemm1<<<gbK, 256, SM_TOTAL>>>(iip, ke, W + 0*32768, w4b, ii2, n_k);

    // join belong CSR, then belong aggregation + F1
    cudaStreamWaitEvent(0, g_aux.evJ2, 0);
    aggregate_kernel<0><<<gAgg, 256>>>(ii2, nb, p_rpB, p_esB, nullptr, n_e);
    fused3_a<<<gbE, 256, SM_TOTAL>>>(ee, nb, W + 1*32768, ek_bias,
                                     W + 2*32768, p_c1, W + 3*32768, w1b,
                                     hiI, sc, n_e);

    // join collab CSR, then collab aggregation + F2
    cudaStreamWaitEvent(0, g_aux.evJ3, 0);
    aggregate_kernel<1><<<gAgg, 256>>>(sc, nc, p_rpC, p_esC, p_ewC, n_e);
    fused3_b<<<gbE, 256, SM_TOTAL>>>(ee, nc, W + 4*32768, ee_bias,
                                     W + 5*32768, p_c2, hiI, W + 6*32768,
                                     combb, out, n_e);
}

// round 9
// speedup vs baseline: 3.8472x; 1.0280x over previous
#include <cuda_runtime.h>
#include <cuda_fp16.h>
#include <cstdint>

typedef __half h16;
#define NK   10000
#define NE   100000
#define D    128
#define DD   (128*128)
#define EDG  1600000

// ---------------- scratch (static __device__ — no allocations allowed) ----------------
__device__ __align__(16) h16 g_ee[NE*D];
__device__ __align__(16) h16 g_ii[NK*D];
__device__ __align__(16) h16 g_ke[NK*D];
__device__ __align__(16) h16 g_ii2[NK*D];
__device__ __align__(16) h16 g_nb[NE*D];
__device__ __align__(16) h16 g_nc[NE*D];
__device__ __align__(16) h16 g_hiI[NE*D];
__device__ __align__(16) h16 g_sc[NE*D];
__device__ __align__(16) h16 g_W[7][128*256];       // per stage [128 n][256 k]
__device__ __align__(16) float g_M1[DD], g_M2[DD], g_M3[DD], g_M4[DD];
__device__ __align__(16) float g_c1[D], g_c2[D];
// CSR (B = belong, C = collab)
__device__ __align__(16) int   g_degB[NE], g_degC[NE];
__device__ __align__(16) int   g_rpB[NE+1], g_rpC[NE+1];
__device__ __align__(16) int   g_curB[NE], g_curC[NE];
__device__ __align__(16) int   g_esrcB[EDG], g_esrcC[EDG];
__device__ __align__(16) float g_ewC[EDG];
__device__ __align__(16) int   g_part[2*128];

// ---------------- host-side aux (streams/events created once) ----------------
struct Aux {
    cudaStream_t s2, s3, s4;
    cudaEvent_t evF, evJ2, evJ3, evJ4;
    Aux() {
        cudaStreamCreateWithFlags(&s2, cudaStreamNonBlocking);
        cudaStreamCreateWithFlags(&s3, cudaStreamNonBlocking);
        cudaStreamCreateWithFlags(&s4, cudaStreamNonBlocking);
        cudaEventCreateWithFlags(&evF,  cudaEventDisableTiming);
        cudaEventCreateWithFlags(&evJ2, cudaEventDisableTiming);
        cudaEventCreateWithFlags(&evJ3, cudaEventDisableTiming);
        cudaEventCreateWithFlags(&evJ4, cudaEventDisableTiming);
    }
};
static Aux g_aux;

// ---------------- small helpers ----------------
__device__ __forceinline__ uint32_t s2u(const void* p) {
    uint32_t a;
    asm("{ .reg .u64 t; cvta.to.shared.u64 t, %1; cvt.u32.u64 %0, t; }" : "=r"(a) : "l"(p));
    return a;
}
__device__ __forceinline__ uint32_t packh(h16 a, h16 b) {
    return ((uint32_t)__half_as_ushort(b) << 16) | (uint32_t)__half_as_ushort(a);
}
__device__ __forceinline__ float hlo(uint32_t u) {
    return __half2float(__ushort_as_half((unsigned short)(u & 0xFFFF)));
}
__device__ __forceinline__ float hhi(uint32_t u) {
    return __half2float(__ushort_as_half((unsigned short)(u >> 16)));
}
__device__ __forceinline__ void ldmx4(uint32_t* r, uint32_t addr) {
    asm volatile("ldmatrix.sync.aligned.m8n8.x4.shared.b16 {%0,%1,%2,%3}, [%4];"
                 : "=r"(r[0]), "=r"(r[1]), "=r"(r[2]), "=r"(r[3]) : "r"(addr));
}
__device__ __forceinline__ void mma16816(float* c, const uint32_t* a, uint32_t b0, uint32_t b1) {
    asm volatile("mma.sync.aligned.m16n8k16.row.col.f32.f16.f16.f32 "
                 "{%0,%1,%2,%3}, {%4,%5,%6,%7}, {%8,%9}, {%0,%1,%2,%3};"
                 : "+f"(c[0]), "+f"(c[1]), "+f"(c[2]), "+f"(c[3])
                 : "r"(a[0]), "r"(a[1]), "r"(a[2]), "r"(a[3]), "r"(b0), "r"(b1));
}
__device__ __forceinline__ void cp16(uint32_t s, const void* g) {
    asm volatile("cp.async.cg.shared.global [%0], [%1], 16;" :: "r"(s), "l"(g));
}

// ---------------- SMEM layout ----------------
#define T_ROW    144
#define CH_B     18432
#define CH_BUF   36864
#define TILE_OFF 73728
#define TT_ROW   272
#define SM_TOTAL 108544
#define CF_ROW   528

// ---------------- generic GEMM pass (identical to R7/R8) ----------------
template <int A1S, int A2S, int ACT, int OUT>
__device__ __forceinline__ void gpass(
    char* smem, uint32_t sb, int tid, int lane, int wid, int mbrow, int M,
    const h16* gA1, const h16* gA2, const h16* w, const float* bias,
    h16* go16, float* go32)
{
    int wr = wid & 3, wc = wid >> 2;

    auto load_chunk = [&](int c, int buf) {
        int k0 = (c & 1) * 64;
        bool a_smem = (c < 2) ? (A1S != 0) : (A2S != 0);
        const h16* A = (c < 2) ? gA1 : gA2;
        if (!a_smem) {
#pragma unroll
            for (int u = 0; u < 4; ++u) {
                int i = u * 256 + tid;
                int row = i >> 3, g = i & 7;
                int grow = mbrow + row;
                if (grow < M)
                    cp16(sb + buf * CH_BUF + row * T_ROW + g * 16,
                         A + (size_t)grow * 128 + k0 + g * 8);
            }
        }
#pragma unroll
        for (int u = 0; u < 4; ++u) {
            int i = u * 256 + tid;
            int n = i >> 3, g = i & 7;
            cp16(sb + buf * CH_BUF + CH_B + n * T_ROW + g * 16,
                 w + n * 256 + c * 64 + g * 8);
        }
        asm volatile("cp.async.commit_group;" ::: "memory");
    };

    load_chunk(0, 0);
    load_chunk(1, 1);

    float acc[2][8][4];
#pragma unroll
    for (int mi = 0; mi < 2; ++mi)
#pragma unroll
        for (int ni = 0; ni < 8; ++ni)
#pragma unroll
            for (int q = 0; q < 4; ++q) acc[mi][ni][q] = 0.f;

    int l15 = lane & 15, lkb = (lane >> 4) * 16;

#pragma unroll
    for (int c = 0; c < 4; ++c) {
        if (c < 3) asm volatile("cp.async.wait_group 1;" ::: "memory");
        else       asm volatile("cp.async.wait_group 0;" ::: "memory");
        __syncthreads();

        int buf = c & 1;
        bool a_smem = (c < 2) ? (A1S != 0) : (A2S != 0);
        uint32_t Ab;
        int arow;
        if (a_smem) {
            Ab = sb + TILE_OFF + (uint32_t)(wr * 32 + l15) * TT_ROW + lkb + (c & 1) * 128;
            arow = TT_ROW;
        } else {
            Ab = sb + buf * CH_BUF + (uint32_t)(wr * 32 + l15) * T_ROW + lkb;
            arow = T_ROW;
        }
        uint32_t Bb = sb + buf * CH_BUF + CH_B + (uint32_t)(wc * 64 + l15) * T_ROW + lkb;
#pragma unroll
        for (int s = 0; s < 4; ++s) {
            uint32_t Aks = Ab + s * 32;
            uint32_t Bks = Bb + s * 32;
            uint32_t A0[4], A1[4];
            ldmx4(A0, Aks);
            ldmx4(A1, Aks + 16 * arow);
            uint32_t B[4][4];
#pragma unroll
            for (int nb = 0; nb < 4; ++nb) ldmx4(B[nb], Bks + nb * (16 * T_ROW));
#pragma unroll
            for (int ni = 0; ni < 8; ++ni) {
                int nb = ni >> 1, hb = ni & 1;
                mma16816(acc[0][ni], A0, B[nb][hb], B[nb][2 + hb]);
                mma16816(acc[1][ni], A1, B[nb][hb], B[nb][2 + hb]);
            }
        }
        __syncthreads();
        if (c + 2 < 4) load_chunk(c + 2, buf);
    }

    int quad = lane >> 2, tq = lane & 3;
    if (OUT == 2) {
#pragma unroll
        for (int ni = 0; ni < 8; ++ni) {
            int cbase = wc * 64 + ni * 8 + tq * 2;
            float bv0 = __ldg(bias + cbase), bv1 = __ldg(bias + cbase + 1);
#pragma unroll
            for (int mi = 0; mi < 2; ++mi)
#pragma unroll
                for (int h = 0; h < 2; ++h) {
                    int row = wr * 32 + mi * 16 + quad + h * 8;
                    float x0 = acc[mi][ni][2 * h + 0] + bv0;
                    float x1 = acc[mi][ni][2 * h + 1] + bv1;
                    if (ACT == 1) { x0 = fmaxf(x0, 0.f); x1 = fmaxf(x1, 0.f); }
                    if (ACT == 2) { x0 = (x0 >= 0.f) ? x0 : 0.2f * x0;
                                    x1 = (x1 >= 0.f) ? x1 : 0.2f * x1; }
                    *(float2*)(smem + row * CF_ROW + cbase * 4) = make_float2(x0, x1);
                }
        }
        __syncthreads();
#pragma unroll
        for (int it = 0; it < 16; ++it) {
            int r = wid * 16 + it;
            int grow = mbrow + r;
            if (grow >= M) continue;
            float4 v = *(float4*)(smem + r * CF_ROW + lane * 16);
            *(float4*)(go32 + (size_t)grow * 128 + lane * 4) = v;
        }
    } else {
#pragma unroll
        for (int ni = 0; ni < 8; ++ni) {
            int cbase = wc * 64 + ni * 8 + tq * 2;
            float bv0 = __ldg(bias + cbase), bv1 = __ldg(bias + cbase + 1);
#pragma unroll
            for (int mi = 0; mi < 2; ++mi)
#pragma unroll
                for (int h = 0; h < 2; ++h) {
                    int row = wr * 32 + mi * 16 + quad + h * 8;
                    float x0 = acc[mi][ni][2 * h + 0] + bv0;
                    float x1 = acc[mi][ni][2 * h + 1] + bv1;
                    if (ACT == 1) { x0 = fmaxf(x0, 0.f); x1 = fmaxf(x1, 0.f); }
                    if (ACT == 2) { x0 = (x0 >= 0.f) ? x0 : 0.2f * x0;
                                    x1 = (x1 >= 0.f) ? x1 : 0.2f * x1; }
                    *(uint32_t*)(smem + TILE_OFF + row * TT_ROW + cbase * 2) =
                        packh(__float2half_rn(x0), __float2half_rn(x1));
                }
        }
        __syncthreads();
        if (OUT == 1) {
            int row2 = lane >> 4, colg = lane & 15;
#pragma unroll
            for (int it = 0; it < 8; ++it) {
                int r = wid * 16 + it * 2 + row2;
                int grow = mbrow + r;
                if (grow >= M) continue;
                uint4 v = *(uint4*)(smem + TILE_OFF + r * TT_ROW + colg * 16);
                *(uint4*)(go16 + (size_t)grow * 128 + colg * 8) = v;
            }
        }
    }
}

// ---------------- GEMM kernels ----------------
__global__ void __launch_bounds__(256, 2) gemm1(
    const h16* __restrict__ a1, const h16* __restrict__ a2,
    const h16* __restrict__ w, const float* __restrict__ bias,
    h16* __restrict__ o, int M)
{
    extern __shared__ char smem[];
    uint32_t sb = s2u(smem);
    gpass<0, 0, 0, 1>(smem, sb, threadIdx.x, threadIdx.x & 31, threadIdx.x >> 5,
                      blockIdx.x * 128, M, a1, a2, w, bias, o, nullptr);
}

__global__ void __launch_bounds__(256, 2) fused3_a(
    const h16* __restrict__ ee, const h16* __restrict__ nb,
    const h16* __restrict__ w0, const float* __restrict__ b0,
    const h16* __restrict__ w1, const float* __restrict__ b1,
    const h16* __restrict__ w2, const float* __restrict__ b2,
    h16* __restrict__ hiI, h16* __restrict__ sc, int M)
{
    extern __shared__ char smem[];
    uint32_t sb = s2u(smem);
    int tid = threadIdx.x, lane = tid & 31, wid = tid >> 5, mb = blockIdx.x * 128;
    gpass<0, 0, 1, 0>(smem, sb, tid, lane, wid, mb, M, ee, nb, w0, b0, nullptr, nullptr);
    gpass<1, 0, 0, 1>(smem, sb, tid, lane, wid, mb, M, nullptr, nb, w1, b1, hiI, nullptr);
    gpass<1, 0, 0, 1>(smem, sb, tid, lane, wid, mb, M, nullptr, ee, w2, b2, sc, nullptr);
}

__global__ void __launch_bounds__(256, 2) fused3_b(
    const h16* __restrict__ ee, const h16* __restrict__ nc,
    const h16* __restrict__ w0, const float* __restrict__ b0,
    const h16* __restrict__ w1, const float* __restrict__ b1,
    const h16* __restrict__ hiI, const h16* __restrict__ w2,
    const float* __restrict__ b2, float* __restrict__ out, int M)
{
    extern __shared__ char smem[];
    uint32_t sb = s2u(smem);
    int tid = threadIdx.x, lane = tid & 31, wid = tid >> 5, mb = blockIdx.x * 128;
    gpass<0, 0, 1, 0>(smem, sb, tid, lane, wid, mb, M, ee, nc, w0, b0, nullptr, nullptr);
    gpass<1, 0, 0, 0>(smem, sb, tid, lane, wid, mb, M, nullptr, nc, w1, b1, nullptr, nullptr);
    gpass<0, 1, 2, 2>(smem, sb, tid, lane, wid, mb, M, hiI, nullptr, w2, b2, nullptr, out);
}

// ---------------- weight split helper ----------------
__device__ __forceinline__ void conv_w_one(int stage, int idx, const float* a, const float* b) {
    int n = idx >> 8, k = idx & 255;
    float v = b ? (k < 128 ? a[n * 128 + k] : b[n * 128 + (k - 128)]) : a[idx];
    g_W[stage][idx] = __float2half_rn(v);
}

// ---------------- prep0: critical-path-only prep (ii/ke + stage0 weights) ----------------
__global__ void prep0(const float* __restrict__ ii, const float* __restrict__ k_emb,
                      const float* __restrict__ w4W) {
    int bid = blockIdx.x, tid = threadIdx.x;
    if (bid < 5000) {
        int i = bid * 256 + tid;
        g_ii[i] = __float2half_rn(ii[i]);
    } else if (bid < 10000) {
        int i = (bid - 5000) * 256 + tid;
        g_ke[i] = __float2half_rn(k_emb[i]);
    } else {
        int idx = (bid - 10000) * 256 + tid;
        g_W[0][idx] = __float2half_rn(w4W[idx]);
    }
}

// ---------------- prepE1: e_emb convert + folds + stages 1,3,4,6 weights ----------------
__global__ void prepE1(const float* __restrict__ e_emb,
                       const float* __restrict__ w2W, const float* __restrict__ w2b,
                       const float* __restrict__ w3W, const float* __restrict__ w3b,
                       const float* __restrict__ ekS1, const float* __restrict__ ekN1,
                       const float* __restrict__ eeS1, const float* __restrict__ eeN1,
                       const float* __restrict__ ekb1, const float* __restrict__ eeb1,
                       const float* __restrict__ ek_self, const float* __restrict__ ek_neigh,
                       const float* __restrict__ w1W, const float* __restrict__ ee_self,
                       const float* __restrict__ ee_neigh, const float* __restrict__ combW) {
    int bid = blockIdx.x, tid = threadIdx.x;
    if (bid < 50000) {
        int i = bid * 256 + tid;
        g_ee[i] = __float2half_rn(e_emb[i]);
    } else if (bid < 50256) {                   // fold_mats
        int lb = bid - 50000;
        int mat = lb >> 6;
        int idx = (lb & 63) * 256 + tid;
        const float* A = (mat < 2) ? w2W : w3W;
        const float* B = (mat == 0) ? ekS1 : (mat == 1) ? ekN1 : (mat == 2) ? eeS1 : eeN1;
        float* O = (mat == 0) ? g_M1 : (mat == 1) ? g_M2 : (mat == 2) ? g_M3 : g_M4;
        int n = idx >> 7, k = idx & 127;
        float acc = 0.f;
#pragma unroll 8
        for (int j = 0; j < 128; ++j)
            acc += A[n * 128 + j] * B[j * 128 + k];
        O[idx] = acc;
    } else if (bid == 50256) {                  // fold_bias
        int t = tid;
        if (t < 128) {
            float a = 0.f, b = 0.f;
#pragma unroll 8
            for (int j = 0; j < 128; ++j) {
                a += w2W[t * 128 + j] * ekb1[j];
                b += w3W[t * 128 + j] * eeb1[j];
            }
            g_c1[t] = a + w2b[t];
            g_c2[t] = b + w3b[t];
        }
    } else {                                    // stages 1, 3, 4, 6 weight splits
        int lb = bid - 50257;
        int which = lb >> 7;
        int idx = (lb & 127) * 256 + tid;
        if (which == 0)      conv_w_one(1, idx, ek_self, ek_neigh);
        else if (which == 1) conv_w_one(3, idx, w1W, nullptr);
        else if (which == 2) conv_w_one(4, idx, ee_self, ee_neigh);
        else                 conv_w_one(6, idx, combW, nullptr);
    }
}

// ---------------- prepE2: stages 2,5 weights (read fold outputs) ----------------
__global__ void prepE2() {
    int bid = blockIdx.x;
    int idx = (bid & 127) * 256 + threadIdx.x;
    if (bid < 128) conv_w_one(2, idx, g_M1, g_M2);
    else           conv_w_one(5, idx, g_M3, g_M4);
}

// ---------------- CSR build (per-graph) ----------------
__global__ void zero_k(int* __restrict__ deg) {
    int i = blockIdx.x * blockDim.x + threadIdx.x;
    if (i < NE) deg[i] = 0;
}
__global__ void count_k(const int* __restrict__ dst, int* __restrict__ deg, int E) {
    int i = blockIdx.x * blockDim.x + threadIdx.x;
    if (i < E) atomicAdd(&deg[dst[i]], 1);
}
__global__ void scanA_k(const int* __restrict__ deg, int* __restrict__ rp,
                        int* __restrict__ part) {
    __shared__ int ws[32];
    int tid = threadIdx.x, lane = tid & 31, wid = tid >> 5;
    int i = blockIdx.x * 1024 + tid;
    int v = (i < NE) ? deg[i] : 0;
    int inc = v;
#pragma unroll
    for (int o = 1; o < 32; o <<= 1) {
        int x = __shfl_up_sync(0xFFFFFFFFu, inc, o);
        if (lane >= o) inc += x;
    }
    if (lane == 31) ws[wid] = inc;
    __syncthreads();
    if (wid == 0) {
        int s = ws[lane];
#pragma unroll
        for (int o = 1; o < 32; o <<= 1) {
            int x = __shfl_up_sync(0xFFFFFFFFu, s, o);
            if (lane >= o) s += x;
        }
        ws[lane] = s;
    }
    __syncthreads();
    int off = wid ? ws[wid - 1] : 0;
    if (i < NE) rp[i] = off + inc - v;
    if (tid == 1023) part[blockIdx.x] = off + inc;
}
__global__ void scanB_k(int* __restrict__ part, int* __restrict__ rp, int nblk) {
    __shared__ int ws[4];
    int tid = threadIdx.x, lane = tid & 31, wid = tid >> 5;
    int v = (tid < nblk) ? part[tid] : 0;
    int inc = v;
#pragma unroll
    for (int o = 1; o < 32; o <<= 1) {
        int x = __shfl_up_sync(0xFFFFFFFFu, inc, o);
        if (lane >= o) inc += x;
    }
    if (lane == 31) ws[wid] = inc;
    __syncthreads();
    int woff = 0;
    for (int w = 0; w < wid; ++w) woff += ws[w];
    int excl = woff + inc - v;
    if (tid < nblk) part[tid] = excl;
    if (tid == nblk - 1) rp[NE] = excl + v;
}
__global__ void scanC_k(int* __restrict__ rp, int* __restrict__ cur,
                        const int* __restrict__ part) {
    int i = blockIdx.x * 1024 + threadIdx.x;
    if (i >= NE) return;
    int val = rp[i] + part[blockIdx.x];
    rp[i] = val;
    cur[i] = val;
}
template <int WEIGHTED>
__global__ void scatter_k(const int* __restrict__ src, const int* __restrict__ dst,
                          const float* __restrict__ ewin, int* __restrict__ cur,
                          int* __restrict__ esrc, float* __restrict__ ewout, int E) {
    int i = blockIdx.x * blockDim.x + threadIdx.x;
    if (i >= E) return;
    int pos = atomicAdd(&cur[dst[i]], 1);
    esrc[pos] = src[i];
    if (WEIGHTED) ewout[pos] = ewin[i];
}

// ---------------- mean aggregation: warp per dst node, 2 edges/iter, uint4 loads ----------------
template <int WEIGHTED>
__global__ void aggregate_kernel(const h16* __restrict__ sh, h16* __restrict__ oh,
                                 const int* __restrict__ rowptr, const int* __restrict__ esrc,
                                 const float* __restrict__ ew, int n) {
    int gw = (blockIdx.x * blockDim.x + threadIdx.x) >> 5;
    int lane = threadIdx.x & 31;
    if (gw >= n) return;
    int s0 = rowptr[gw], s1 = rowptr[gw + 1];
    int half = lane >> 4, l16 = lane & 15;
    float a[8];
#pragma unroll
    for (int d = 0; d < 8; ++d) a[d] = 0.f;
    int j = s0;
    for (; j + 1 < s1; j += 2) {
        int e = j + half;
        int sidx = esrc[e];
        uint4 u = *(const uint4*)(sh + (size_t)sidx * D + l16 * 8);
        float w = WEIGHTED ? ew[e] : 1.0f;
        a[0] += hlo(u.x) * w; a[1] += hhi(u.x) * w;
        a[2] += hlo(u.y) * w; a[3] += hhi(u.y) * w;
        a[4] += hlo(u.z) * w; a[5] += hhi(u.z) * w;
        a[6] += hlo(u.w) * w; a[7] += hhi(u.w) * w;
    }
    if (j < s1 && half == 0) {                  // odd tail edge: half 0 only
        int sidx = esrc[j];
        uint4 u = *(const uint4*)(sh + (size_t)sidx * D + l16 * 8);
        float w = WEIGHTED ? ew[j] : 1.0f;
        a[0] += hlo(u.x) * w; a[1] += hhi(u.x) * w;
        a[2] += hlo(u.y) * w; a[3] += hhi(u.y) * w;
        a[4] += hlo(u.z) * w; a[5] += hhi(u.z) * w;
        a[6] += hlo(u.w) * w; a[7] += hhi(u.w) * w;
    }
#pragma unroll
    for (int d = 0; d < 8; ++d) a[d] += __shfl_xor_sync(0xFFFFFFFFu, a[d], 16);
    if (half == 0) {
        float inv = 1.0f / fmaxf((float)(s1 - s0), 1.0f);
        uint4 o;
        o.x = packh(__float2half_rn(a[0] * inv), __float2half_rn(a[1] * inv));
        o.y = packh(__float2half_rn(a[2] * inv), __float2half_rn(a[3] * inv));
        o.z = packh(__float2half_rn(a[4] * inv), __float2half_rn(a[5] * inv));
        o.w = packh(__float2half_rn(a[6] * inv), __float2half_rn(a[7] * inv));
        *(uint4*)(oh + (size_t)gw * D + l16 * 8) = o;
    }
}

// ---------------- launch ----------------
extern "C" void kernel_launch(void* const* d_in, const int* in_sizes, int n_in,
                              void* d_out, int out_size) {
    const float* ii      = (const float*)d_in[0];
    const float* e_emb   = (const float*)d_in[1];
    const float* k_emb   = (const float*)d_in[2];
    const float* cf_ew   = (const float*)d_in[3];
    const int*   b_src   = (const int*)d_in[4];
    const int*   b_dst   = (const int*)d_in[5];
    const int*   c_src   = (const int*)d_in[6];
    const int*   c_dst   = (const int*)d_in[7];
    const float* ek_self = (const float*)d_in[8];
    const float* ek_neigh= (const float*)d_in[9];
    const float* ek_bias = (const float*)d_in[10];
    const float* ee_self = (const float*)d_in[11];
    const float* ee_neigh= (const float*)d_in[12];
    const float* ee_bias = (const float*)d_in[13];
    const float* w1W = (const float*)d_in[14];
    const float* w1b = (const float*)d_in[15];
    const float* w2W = (const float*)d_in[16];
    const float* w2b = (const float*)d_in[17];
    const float* w3W = (const float*)d_in[18];
    const float* w3b = (const float*)d_in[19];
    const float* w4W = (const float*)d_in[20];
    const float* w4b = (const float*)d_in[21];
    const float* combW = (const float*)d_in[22];
    const float* combb = (const float*)d_in[23];
    float* out = (float*)d_out;

    int n_k = in_sizes[0] / D;
    int n_e = in_sizes[1] / D;
    int E   = in_sizes[4];

    h16 *ee, *iip, *ke, *ii2, *nb, *nc, *hiI, *sc, *W;
    float *p_c1, *p_c2, *p_ewC;
    int *p_rpB, *p_rpC, *p_esB, *p_esC, *p_degB, *p_degC, *p_curB, *p_curC, *p_part;
    cudaGetSymbolAddress((void**)&ee,  g_ee);
    cudaGetSymbolAddress((void**)&iip, g_ii);
    cudaGetSymbolAddress((void**)&ke,  g_ke);
    cudaGetSymbolAddress((void**)&ii2, g_ii2);
    cudaGetSymbolAddress((void**)&nb,  g_nb);
    cudaGetSymbolAddress((void**)&nc,  g_nc);
    cudaGetSymbolAddress((void**)&hiI, g_hiI);
    cudaGetSymbolAddress((void**)&sc,  g_sc);
    cudaGetSymbolAddress((void**)&W,   g_W);
    cudaGetSymbolAddress((void**)&p_c1, g_c1);   cudaGetSymbolAddress((void**)&p_c2, g_c2);
    cudaGetSymbolAddress((void**)&p_rpB, g_rpB); cudaGetSymbolAddress((void**)&p_rpC, g_rpC);
    cudaGetSymbolAddress((void**)&p_esB, g_esrcB); cudaGetSymbolAddress((void**)&p_esC, g_esrcC);
    cudaGetSymbolAddress((void**)&p_ewC, g_ewC);
    cudaGetSymbolAddress((void**)&p_degB, g_degB); cudaGetSymbolAddress((void**)&p_degC, g_degC);
    cudaGetSymbolAddress((void**)&p_curB, g_curB); cudaGetSymbolAddress((void**)&p_curC, g_curC);
    cudaGetSymbolAddress((void**)&p_part, g_part);

    cudaFuncSetAttribute(gemm1,    cudaFuncAttributeMaxDynamicSharedMemorySize, SM_TOTAL);
    cudaFuncSetAttribute(fused3_a, cudaFuncAttributeMaxDynamicSharedMemorySize, SM_TOTAL);
    cudaFuncSetAttribute(fused3_b, cudaFuncAttributeMaxDynamicSharedMemorySize, SM_TOTAL);

    int gE   = (E + 255) / 256;
    int gNe  = (n_e + 255) / 256;
    int gSc  = (n_e + 1023) / 1024;
    int gAgg = (n_e * 32 + 255) / 256;
    int gbK  = (n_k + 127) / 128;
    int gbE  = (n_e + 127) / 128;

    // ---- fork ----
    cudaEventRecord(g_aux.evF, 0);
    cudaStreamWaitEvent(g_aux.s2, g_aux.evF, 0);
    cudaStreamWaitEvent(g_aux.s3, g_aux.evF, 0);
    cudaStreamWaitEvent(g_aux.s4, g_aux.evF, 0);

    // s2: belong CSR
    zero_k<<<gNe, 256, 0, g_aux.s2>>>(p_degB);
    count_k<<<gE, 256, 0, g_aux.s2>>>(b_dst, p_degB, E);
    scanA_k<<<gSc, 1024, 0, g_aux.s2>>>(p_degB, p_rpB, p_part);
    scanB_k<<<1, 128, 0, g_aux.s2>>>(p_part, p_rpB, gSc);
    scanC_k<<<gSc, 1024, 0, g_aux.s2>>>(p_rpB, p_curB, p_part);
    scatter_k<0><<<gE, 256, 0, g_aux.s2>>>(b_src, b_dst, nullptr, p_curB, p_esB, nullptr, E);
    cudaEventRecord(g_aux.evJ2, g_aux.s2);

    // s3: collab CSR
    zero_k<<<gNe, 256, 0, g_aux.s3>>>(p_degC);
    count_k<<<gE, 256, 0, g_aux.s3>>>(c_dst, p_degC, E);
    scanA_k<<<gSc, 1024, 0, g_aux.s3>>>(p_degC, p_rpC, p_part + 128);
    scanB_k<<<1, 128, 0, g_aux.s3>>>(p_part + 128, p_rpC, gSc);
    scanC_k<<<gSc, 1024, 0, g_aux.s3>>>(p_rpC, p_curC, p_part + 128);
    scatter_k<1><<<gE, 256, 0, g_aux.s3>>>(c_src, c_dst, cf_ew, p_curC, p_esC, p_ewC, E);
    cudaEventRecord(g_aux.evJ3, g_aux.s3);

    // s4: heavy prep (e_emb, folds, stage 1-6 weights) off the critical path
    prepE1<<<50769, 256, 0, g_aux.s4>>>(e_emb, w2W, w2b, w3W, w3b,
                                        ek_self + DD, ek_neigh + DD, ee_self + DD, ee_neigh + DD,
                                        ek_bias + D, ee_bias + D,
                                        ek_self, ek_neigh, w1W, ee_self, ee_neigh, combW);
    prepE2<<<256, 256, 0, g_aux.s4>>>();
    cudaEventRecord(g_aux.evJ4, g_aux.s4);

    // main stream: minimal prep + stage0 GEMM
    prep0<<<10128, 256>>>(ii, k_emb, w4W);
    gemm1<<<gbK, 256, SM_TOTAL>>>(iip, ke, W + 0*32768, w4b, ii2, n_k);

    // join belong CSR → aggB; join heavy prep → F1
    cudaStreamWaitEvent(0, g_aux.evJ2, 0);
    aggregate_kernel<0><<<gAgg, 256>>>(ii2, nb, p_rpB, p_esB, nullptr, n_e);
    cudaStreamWaitEvent(0, g_aux.evJ4, 0);
    fused3_a<<<gbE, 256, SM_TOTAL>>>(ee, nb, W + 1*32768, ek_bias,
                                     W + 2*32768, p_c1, W + 3*32768, w1b,
                                     hiI, sc, n_e);

    // join collab CSR → aggC → F2
    cudaStreamWaitEvent(0, g_aux.evJ3, 0);
    aggregate_kernel<1><<<gAgg, 256>>>(sc, nc, p_rpC, p_esC, p_ewC, n_e);
    fused3_b<<<gbE, 256, SM_TOTAL>>>(ee, nc, W + 4*32768, ee_bias,
                                     W + 5*32768, p_c2, hiI, W + 6*32768,
                                     combb, out, n_e);
}